// round 13
// baseline (speedup 1.0000x reference)
#include <cuda_runtime.h>
#include <cstdint>

#define NB 4
#define NC 64
#define NH 128
#define NW 128
#define NPIX (NH*NW)
#define NWIN 31
#define NL (NWIN*NWIN)

typedef unsigned long long u64;

// proj slot order: 0=ql 1=kh 2=vh 3=qh 4=kl 5=vl  (dir0 uses 0,1,2; dir1 uses 3,4,5)
// NOTE: all slots stored PRE-ROUNDED to tf32 bit patterns (consumed only by attn MMA).
__device__ float g_proj[6*NB*NC*NPIX];
__device__ float g_win_l[(size_t)NB*NL*64*64];   // [b][l][n][c] per-window outputs
__device__ float g_win_h[(size_t)NB*NL*64*64];
__device__ float g_mean[NB*NC];
__device__ float g_sgate[NB*NC];

// ---------------- packed f32x2 helpers ----------------
__device__ __forceinline__ u64 pk2(float lo, float hi) {
    u64 r;
    asm("mov.b64 %0,{%1,%2};" : "=l"(r) : "f"(lo), "f"(hi));
    return r;
}
__device__ __forceinline__ void upk2(float& lo, float& hi, u64 v) {
    asm("mov.b64 {%0,%1},%2;" : "=f"(lo), "=f"(hi) : "l"(v));
}
__device__ __forceinline__ u64 fma2(u64 a, u64 b, u64 c) {
    u64 d;
    asm("fma.rn.f32x2 %0,%1,%2,%3;" : "=l"(d) : "l"(a), "l"(b), "l"(c));
    return d;
}

// ---------------- tf32 mma helpers ----------------
__device__ __forceinline__ uint32_t tf32r(float f) {
    uint32_t r;
    asm("cvt.rna.tf32.f32 %0,%1;" : "=r"(r) : "f"(f));
    return r;
}
__device__ __forceinline__ float tfr(float x) { return __uint_as_float(tf32r(x)); }
__device__ __forceinline__ float ex2(float x) {
    float r;
    asm("ex2.approx.f32 %0,%1;" : "=f"(r) : "f"(x));
    return r;
}
__device__ __forceinline__ void mma8(float* d, const uint32_t* a, uint32_t b0, uint32_t b1) {
    asm volatile(
        "mma.sync.aligned.m16n8k8.row.col.f32.tf32.tf32.f32 "
        "{%0,%1,%2,%3},{%4,%5,%6,%7},{%8,%9},{%0,%1,%2,%3};"
        : "+f"(d[0]), "+f"(d[1]), "+f"(d[2]), "+f"(d[3])
        : "r"(a[0]), "r"(a[1]), "r"(a[2]), "r"(a[3]), "r"(b0), "r"(b1));
}

// ---------------- SE: per-channel global mean ----------------
__global__ void mean_kernel(const float* __restrict__ high) {
    int bc = blockIdx.x;
    const float* p = high + (size_t)bc * NPIX;
    float s = 0.f;
    for (int i = threadIdx.x; i < NPIX; i += 256) s += p[i];
    __shared__ float red[256];
    red[threadIdx.x] = s; __syncthreads();
    for (int k = 128; k > 0; k >>= 1) {
        if (threadIdx.x < k) red[threadIdx.x] += red[threadIdx.x + k];
        __syncthreads();
    }
    if (threadIdx.x == 0) g_mean[bc] = red[0] * (1.f/NPIX);
}

// ---------------- SE: gate per (b,c) ----------------
__global__ void se_kernel(const float* __restrict__ w10, const float* __restrict__ w20,
                          const float* __restrict__ w11, const float* __restrict__ w21,
                          const float* __restrict__ w12, const float* __restrict__ w22) {
    int t = threadIdx.x;
    int b = t >> 6, c = t & 63;
    int g  = (c < 22) ? 0 : ((c < 43) ? 1 : 2);
    int of = (g == 0) ? 0 : ((g == 1) ? 22 : 43);
    int gc = (g == 0) ? 22 : 21;
    const float* w1 = (g==0) ? w10 : ((g==1) ? w11 : w12);
    const float* w2 = (g==0) ? w20 : ((g==1) ? w21 : w22);
    float h = 0.f;
    for (int j = 0; j < gc; j++) h += g_mean[b*64 + of + j] * w1[j];
    h = fmaxf(h, 0.f);
    float v = h * w2[c - of];
    g_sgate[t] = 1.f / (1.f + __expf(-v));
}

// ---------------- projections: 3 stages of 2 weights; outputs pre-rounded tf32 ----------------
#define WTS 68
#define QS 0.36067376022224085f
__global__ void __launch_bounds__(256,3) proj_kernel(
    const float* __restrict__ low, const float* __restrict__ high,
    const float* __restrict__ w_ql, const float* __restrict__ w_kh,
    const float* __restrict__ w_vh, const float* __restrict__ w_qh,
    const float* __restrict__ w_kl, const float* __restrict__ w_vl)
{
    extern __shared__ float sm[];
    float* xl = sm;            // 4096
    float* xh = sm + 4096;     // 4096
    float* wb = sm + 8192;     // 2 * 64*68 = 8704

    int t = threadIdx.x;
    int pix0 = blockIdx.x * 64;
    int b = blockIdx.y;

    for (int i4 = t; i4 < 1024; i4 += 256) {
        int c = i4 >> 4, pp = (i4 & 15) * 4;
        size_t gi = (size_t)(b*NC + c)*NPIX + pix0 + pp;
        float4 vl = *(const float4*)(low + gi);
        float4 vh = *(const float4*)(high + gi);
        float gt = g_sgate[b*64 + c];
        vh.x *= gt; vh.y *= gt; vh.z *= gt; vh.w *= gt;
        *(float4*)(xl + c*64 + pp) = vl;
        *(float4*)(xh + c*64 + pp) = vh;
    }

    int ot = (t >> 4) << 2;
    int nb = (t & 15) << 2;

    // s0: (0=ql[xl,QS], 4=kl[xl])   s1: (1=kh[xh], 2=vh[xh])   s2: (5=vl[xl], 3=qh[xh,QS])
    const float* WA[3]; const float* WB[3];
    WA[0] = w_ql; WB[0] = w_kl;
    WA[1] = w_kh; WB[1] = w_vh;
    WA[2] = w_vl; WB[2] = w_qh;
    const int slotA[3] = {0, 1, 5};
    const int slotB[3] = {4, 2, 3};

    for (int s = 0; s < 3; s++) {
        __syncthreads();
        bool scaleA = (s == 0), scaleB = (s == 2);
        for (int i = t; i < 8192; i += 256) {
            int p = i >> 12, j = i & 4095;
            int o = j >> 6, c = j & 63;
            float wv = (p == 0) ? WA[s][j] : WB[s][j];
            if ((p == 0 && scaleA) || (p == 1 && scaleB)) wv *= QS;
            wb[p*4352 + c*WTS + o] = wv;
        }
        __syncthreads();

        const float* XA = (s == 2) ? xl : ((s == 0) ? xl : xh);
        const float* XB = (s == 2) ? xh : ((s == 0) ? xl : xh);
        bool sameX = (s != 2);

        u64 acc2[2][4][2];
        #pragma unroll
        for (int p = 0; p < 2; p++)
            #pragma unroll
            for (int n = 0; n < 4; n++) { acc2[p][n][0] = 0ULL; acc2[p][n][1] = 0ULL; }

        if (sameX) {
            #pragma unroll 4
            for (int c = 0; c < 64; c++) {
                float4 x4 = *(const float4*)(XA + c*64 + nb);
                u64 xd0 = pk2(x4.x, x4.x);
                u64 xd1 = pk2(x4.y, x4.y);
                u64 xd2 = pk2(x4.z, x4.z);
                u64 xd3 = pk2(x4.w, x4.w);
                #pragma unroll
                for (int p = 0; p < 2; p++) {
                    ulonglong2 w2v = *(const ulonglong2*)(wb + p*4352 + c*WTS + ot);
                    acc2[p][0][0] = fma2(xd0, w2v.x, acc2[p][0][0]);
                    acc2[p][0][1] = fma2(xd0, w2v.y, acc2[p][0][1]);
                    acc2[p][1][0] = fma2(xd1, w2v.x, acc2[p][1][0]);
                    acc2[p][1][1] = fma2(xd1, w2v.y, acc2[p][1][1]);
                    acc2[p][2][0] = fma2(xd2, w2v.x, acc2[p][2][0]);
                    acc2[p][2][1] = fma2(xd2, w2v.y, acc2[p][2][1]);
                    acc2[p][3][0] = fma2(xd3, w2v.x, acc2[p][3][0]);
                    acc2[p][3][1] = fma2(xd3, w2v.y, acc2[p][3][1]);
                }
            }
        } else {
            #pragma unroll 4
            for (int c = 0; c < 64; c++) {
                float4 xa4 = *(const float4*)(XA + c*64 + nb);
                float4 xb4 = *(const float4*)(XB + c*64 + nb);
                u64 xa0 = pk2(xa4.x, xa4.x), xa1 = pk2(xa4.y, xa4.y);
                u64 xa2 = pk2(xa4.z, xa4.z), xa3 = pk2(xa4.w, xa4.w);
                u64 xb0 = pk2(xb4.x, xb4.x), xb1 = pk2(xb4.y, xb4.y);
                u64 xb2 = pk2(xb4.z, xb4.z), xb3 = pk2(xb4.w, xb4.w);
                ulonglong2 wa = *(const ulonglong2*)(wb + c*WTS + ot);
                ulonglong2 wv = *(const ulonglong2*)(wb + 4352 + c*WTS + ot);
                acc2[0][0][0] = fma2(xa0, wa.x, acc2[0][0][0]);
                acc2[0][0][1] = fma2(xa0, wa.y, acc2[0][0][1]);
                acc2[0][1][0] = fma2(xa1, wa.x, acc2[0][1][0]);
                acc2[0][1][1] = fma2(xa1, wa.y, acc2[0][1][1]);
                acc2[0][2][0] = fma2(xa2, wa.x, acc2[0][2][0]);
                acc2[0][2][1] = fma2(xa2, wa.y, acc2[0][2][1]);
                acc2[0][3][0] = fma2(xa3, wa.x, acc2[0][3][0]);
                acc2[0][3][1] = fma2(xa3, wa.y, acc2[0][3][1]);
                acc2[1][0][0] = fma2(xb0, wv.x, acc2[1][0][0]);
                acc2[1][0][1] = fma2(xb0, wv.y, acc2[1][0][1]);
                acc2[1][1][0] = fma2(xb1, wv.x, acc2[1][1][0]);
                acc2[1][1][1] = fma2(xb1, wv.y, acc2[1][1][1]);
                acc2[1][2][0] = fma2(xb2, wv.x, acc2[1][2][0]);
                acc2[1][2][1] = fma2(xb2, wv.y, acc2[1][2][1]);
                acc2[1][3][0] = fma2(xb3, wv.x, acc2[1][3][0]);
                acc2[1][3][1] = fma2(xb3, wv.y, acc2[1][3][1]);
            }
        }

        int sl[2]; sl[0] = slotA[s]; sl[1] = slotB[s];
        #pragma unroll
        for (int p = 0; p < 2; p++) {
            float lo0[4], hi0[4], lo1[4], hi1[4];
            #pragma unroll
            for (int n = 0; n < 4; n++) {
                upk2(lo0[n], hi0[n], acc2[p][n][0]);
                upk2(lo1[n], hi1[n], acc2[p][n][1]);
            }
            size_t base = (size_t)sl[p]*NB*NC*NPIX + (size_t)(b*NC)*NPIX + pix0 + nb;
            *(float4*)(g_proj + base + (size_t)(ot+0)*NPIX) =
                make_float4(tfr(lo0[0]), tfr(lo0[1]), tfr(lo0[2]), tfr(lo0[3]));
            *(float4*)(g_proj + base + (size_t)(ot+1)*NPIX) =
                make_float4(tfr(hi0[0]), tfr(hi0[1]), tfr(hi0[2]), tfr(hi0[3]));
            *(float4*)(g_proj + base + (size_t)(ot+2)*NPIX) =
                make_float4(tfr(lo1[0]), tfr(lo1[1]), tfr(lo1[2]), tfr(lo1[3]));
            *(float4*)(g_proj + base + (size_t)(ot+3)*NPIX) =
                make_float4(tfr(hi1[0]), tfr(hi1[1]), tfr(hi1[2]), tfr(hi1[3]));
        }
    }
}

// ---------------- attention: tf32 MMA v5 (pre-rounded inputs, shfl softmax inv) ----------------
#define KSTR 72
#define VSTR 68
#define KHSZ (16*KSTR)
#define VHSZ (16*VSTR)
#define SMEM_ATTN_WORDS (4*KHSZ + 4*VHSZ)

__global__ void __launch_bounds__(128, 6) attn_kernel()
{
    extern __shared__ uint32_t smu[];
    uint32_t* kbuf = smu;                      // 4*KHSZ
    uint32_t* vbuf = smu + 4*KHSZ;             // 4*VHSZ

    int t = threadIdx.x;
    int l = blockIdx.x, dir = blockIdx.y, b = blockIdx.z;
    int y0 = (l / NWIN) * 4, x0 = (l % NWIN) * 4;

    // stage K and V (already tf32 bit patterns; pure copy)
    for (int i4 = t; i4 < 2048; i4 += 128) {
        int p = i4 >> 10, rem = i4 & 1023;       // p: 0=k 1=v
        int slot = dir*3 + 1 + p;
        int c = rem >> 4, q4 = rem & 15;
        int r = q4 >> 1, cc = (q4 & 1) * 4;
        int n = r*8 + cc;
        int h = c >> 4, d = c & 15;
        size_t gi = ((size_t)slot*NB*NC + (size_t)(b*NC + c))*NPIX + (size_t)(y0 + r)*NW + x0 + cc;
        uint4 e = *(const uint4*)(g_proj + gi);
        uint32_t* dst = (p ? (vbuf + h*VHSZ + d*VSTR) : (kbuf + h*KHSZ + d*KSTR)) + n;
        *(uint4*)dst = e;
    }
    __syncthreads();

    int h = t >> 5, lane = t & 31;
    int gid = lane >> 2, tig = lane & 3;
    int sig = (gid & 1) ? ((gid >> 1) + 4) : (gid >> 1);   // sigma(gid)

    const uint32_t* kf = kbuf + h*KHSZ;
    const uint32_t* vf = vbuf + h*VHSZ;
    const float* Qg = g_proj + ((size_t)(dir ? 3 : 0)*NB*NC + (size_t)(b*NC + h*16))*NPIX;
    float* wdst = (dir ? g_win_h : g_win_l) + (size_t)(b*NL + l)*4096;  // [n][c]

    #pragma unroll
    for (int nt = 0; nt < 4; nt++) {
        int nbase = nt*16;
        size_t pA = (size_t)(y0 + 2*nt)*NW + x0 + gid;   // pixel for n = nbase+gid
        size_t pB = pA + NW;                              // pixel for n = nbase+gid+8

        // ---- Q A-fragments (already tf32) from gmem ----
        uint32_t qh[2][4];
        #pragma unroll
        for (int kq = 0; kq < 2; kq++) {
            int d0 = kq*8 + tig;
            qh[kq][0] = __float_as_uint(Qg[(size_t)d0*NPIX     + pA]);
            qh[kq][1] = __float_as_uint(Qg[(size_t)d0*NPIX     + pB]);
            qh[kq][2] = __float_as_uint(Qg[(size_t)(d0+4)*NPIX + pA]);
            qh[kq][3] = __float_as_uint(Qg[(size_t)(d0+4)*NPIX + pB]);
        }

        float o0[4] = {0.f,0.f,0.f,0.f};   // O tile, n = nbase + 0..7
        float o1[4] = {0.f,0.f,0.f,0.f};   // O tile, n = nbase + 8..15
        float rs0 = 0.f, rs1 = 0.f;

        #pragma unroll
        for (int m8 = 0; m8 < 64; m8 += 8) {
            // ---- S tile [n16 x m8]: 2 MMA ----
            float c[4] = {0.f,0.f,0.f,0.f};
            #pragma unroll
            for (int kq = 0; kq < 2; kq++) {
                uint32_t kk0 = kf[(kq*8+tig)*KSTR   + m8 + sig];
                uint32_t kk1 = kf[(kq*8+tig+4)*KSTR + m8 + sig];
                mma8(c, qh[kq], kk0, kk1);
            }
            // ---- exp, rowsum, P 1-term ----
            float e0 = ex2(c[0]), e1 = ex2(c[1]), e2 = ex2(c[2]), e3 = ex2(c[3]);
            rs0 += e0 + e1;
            rs1 += e2 + e3;
            uint32_t p0 = tf32r(e0), p1 = tf32r(e1), p2 = tf32r(e2), p3 = tf32r(e3);
            // ---- V A-fragments (pre-converted) ----
            uint32_t va[4];
            va[0] = vf[gid*VSTR     + m8 + tig    ];
            va[1] = vf[(gid+8)*VSTR + m8 + tig    ];
            va[2] = vf[gid*VSTR     + m8 + tig + 4];
            va[3] = vf[(gid+8)*VSTR + m8 + tig + 4];
            // ---- AV: 2 MMA ----
            mma8(o0, va, p0, p1);
            mma8(o1, va, p2, p3);
        }
        // ---- full rowsums (reduce across tig) ----
        rs0 += __shfl_xor_sync(0xffffffffu, rs0, 1);
        rs0 += __shfl_xor_sync(0xffffffffu, rs0, 2);
        rs1 += __shfl_xor_sync(0xffffffffu, rs1, 1);
        rs1 += __shfl_xor_sync(0xffffffffu, rs1, 2);
        // lane holds O for n-cols 2tig, 2tig+1 (rows of rowsum owner gid'=2tig / 2tig+1)
        float sA0 = __shfl_sync(0xffffffffu, rs0, (lane & 28) | 0, 32);   // placeholder overwritten below
        // correct sources: rowsum for n = nbase+j lives as rs0 (j<8) / rs1 (j>=8) in lanes gid=j
        sA0          = __shfl_sync(0xffffffffu, rs0, 8*tig);       // n = 2tig
        float sA1    = __shfl_sync(0xffffffffu, rs0, 8*tig + 4);   // n = 2tig+1
        float sB0    = __shfl_sync(0xffffffffu, rs1, 8*tig);       // n = 8+2tig
        float sB1    = __shfl_sync(0xffffffffu, rs1, 8*tig + 4);   // n = 9+2tig
        float iA0 = 1.f / sA0, iA1 = 1.f / sA1;
        float iB0 = 1.f / sB0, iB1 = 1.f / sB1;
        // ---- normalize + per-window store (no atomics) ----
        {
            int n0 = nbase + 2*tig;
            float* w0 = wdst + (size_t)n0*64 + h*16;
            w0[gid]          = o0[0]*iA0;
            w0[64 + gid]     = o0[1]*iA1;
            w0[gid + 8]      = o0[2]*iA0;
            w0[64 + gid + 8] = o0[3]*iA1;
            float* w1 = wdst + (size_t)(n0+8)*64 + h*16;
            w1[gid]          = o1[0]*iB0;
            w1[64 + gid]     = o1[1]*iB1;
            w1[gid + 8]      = o1[2]*iB0;
            w1[64 + gid + 8] = o1[3]*iB1;
        }
    }
}

// ---------------- epilogue: gather <=4 windows per pixel, 1x1 proj + residual ----------------
__global__ void __launch_bounds__(256) epi_kernel(
    const float* __restrict__ low, const float* __restrict__ high,
    const float* __restrict__ wpl, const float* __restrict__ wph,
    float* __restrict__ out)
{
    extern __shared__ float sm[];
    float* tl = sm;                  // 64*65 = 4160
    float* th = sm + 4160;           // 4160
    float* wl = sm + 8320;           // 64*68 = 4352
    float* wh = sm + 8320 + 4352;    // 4352 (total 17024 floats)

    int t = threadIdx.x;
    int chunk = blockIdx.x;          // 1024 chunks: 256 per batch, 64 px each
    int b = chunk >> 8;
    int pix0 = (chunk & 255) * 64;

    for (int i = t; i < 4096; i += 256) {
        int o = i >> 6, c = i & 63;
        wl[c*WTS + o] = wpl[i];
        wh[c*WTS + o] = wph[i];
    }

    int cid = t & 63, pg = t >> 6;
    for (int it = 0; it < 16; it++) {
        int px = it*4 + pg;
        int pix = pix0 + px;
        int y = pix >> 7, x = pix & 127;
        int iyl = (y >= 8) ? ((y - 4) >> 2) : 0;
        int iyh = y >> 2; if (iyh > 30) iyh = 30;
        int ixl = (x >= 8) ? ((x - 4) >> 2) : 0;
        int ixh = x >> 2; if (ixh > 30) ixh = 30;
        float sl = 0.f, sh = 0.f;
        for (int iy = iyl; iy <= iyh; iy++) {
            for (int ix = ixl; ix <= ixh; ix++) {
                int ll = iy*NWIN + ix;
                int n = (y - 4*iy)*8 + (x - 4*ix);
                size_t base = ((size_t)(b*NL + ll)*64 + n)*64 + cid;
                sl += g_win_l[base];
                sh += g_win_h[base];
            }
        }
        float ic = 1.f / (float)((iyh - iyl + 1) * (ixh - ixl + 1));
        tl[cid*65 + px] = sl * ic;
        th[cid*65 + px] = sh * ic;
    }
    __syncthreads();

    int px = t & 63, og = (t >> 6) * 16;
    u64 rl2[8], rh2[8];
    #pragma unroll
    for (int j = 0; j < 8; j++) { rl2[j] = 0ULL; rh2[j] = 0ULL; }

    #pragma unroll 4
    for (int c = 0; c < 64; c++) {
        float tv = tl[c*65 + px];
        float hv = th[c*65 + px];
        u64 tv2 = pk2(tv, tv);
        u64 hv2 = pk2(hv, hv);
        const ulonglong2* wlr = (const ulonglong2*)(wl + c*WTS + og);
        const ulonglong2* whr = (const ulonglong2*)(wh + c*WTS + og);
        #pragma unroll
        for (int o4 = 0; o4 < 4; o4++) {
            ulonglong2 a2 = wlr[o4];
            ulonglong2 b2 = whr[o4];
            rl2[o4*2]   = fma2(tv2, a2.x, rl2[o4*2]);
            rl2[o4*2+1] = fma2(tv2, a2.y, rl2[o4*2+1]);
            rh2[o4*2]   = fma2(hv2, b2.x, rh2[o4*2]);
            rh2[o4*2+1] = fma2(hv2, b2.y, rh2[o4*2+1]);
        }
    }
    size_t half = (size_t)NB*NC*NPIX;
    int pix = pix0 + px;
    #pragma unroll
    for (int j = 0; j < 8; j++) {
        float a, bb; upk2(a, bb, rl2[j]);
        float c2, d2; upk2(c2, d2, rh2[j]);
        int o0 = og + j*2;
        size_t gi0 = (size_t)(b*NC + o0)*NPIX + pix;
        size_t gi1 = (size_t)(b*NC + o0 + 1)*NPIX + pix;
        out[gi0]        = low[gi0]  + a;
        out[gi1]        = low[gi1]  + bb;
        out[half + gi0] = high[gi0] + c2;
        out[half + gi1] = high[gi1] + d2;
    }
}

extern "C" void kernel_launch(void* const* d_in, const int* in_sizes, int n_in,
                              void* d_out, int out_size)
{
    (void)in_sizes; (void)n_in; (void)out_size;
    const float* low  = (const float*)d_in[0];
    const float* high = (const float*)d_in[1];
    const float* w_ql = (const float*)d_in[2];
    const float* w_kh = (const float*)d_in[3];
    const float* w_vh = (const float*)d_in[4];
    const float* w_qh = (const float*)d_in[5];
    const float* w_kl = (const float*)d_in[6];
    const float* w_vl = (const float*)d_in[7];
    const float* wpl  = (const float*)d_in[8];
    const float* wph  = (const float*)d_in[9];

    int proj_smem = (8192 + 8704) * 4;        // 67.6 KB
    int attn_smem = SMEM_ATTN_WORDS * 4;      // 36.3 KB
    int epi_smem  = 17024 * 4;                // 66.5 KB

    cudaFuncSetAttribute(proj_kernel, cudaFuncAttributeMaxDynamicSharedMemorySize, proj_smem);
    cudaFuncSetAttribute(attn_kernel, cudaFuncAttributeMaxDynamicSharedMemorySize, attn_smem);
    cudaFuncSetAttribute(epi_kernel,  cudaFuncAttributeMaxDynamicSharedMemorySize, epi_smem);

    mean_kernel<<<NB*NC, 256>>>(high);
    se_kernel<<<1, 256>>>((const float*)d_in[10], (const float*)d_in[11],
                          (const float*)d_in[12], (const float*)d_in[13],
                          (const float*)d_in[14], (const float*)d_in[15]);
    proj_kernel<<<dim3(NPIX/64, NB), 256, proj_smem>>>(low, high, w_ql, w_kh, w_vh, w_qh, w_kl, w_vl);
    attn_kernel<<<dim3(NL, 2, NB), 128, attn_smem>>>();
    epi_kernel<<<1024, 256, epi_smem>>>(low, high, wpl, wph, (float*)d_out);
}

// round 14
// speedup vs baseline: 1.0047x; 1.0047x over previous
#include <cuda_runtime.h>
#include <cstdint>

#define NB 4
#define NC 64
#define NH 128
#define NW 128
#define NPIX (NH*NW)
#define NWIN 31
#define NL (NWIN*NWIN)

typedef unsigned long long u64;

// proj slot order: 0=ql 1=kh 2=vh 3=qh 4=kl 5=vl  (dir0 uses 0,1,2; dir1 uses 3,4,5)
__device__ float g_proj[6*NB*NC*NPIX];
__device__ float g_win_l[(size_t)NB*NL*64*64];   // [b][l][n][c] per-window outputs
__device__ float g_win_h[(size_t)NB*NL*64*64];
__device__ float g_mean[NB*NC];
__device__ float g_sgate[NB*NC];

// ---------------- packed f32x2 helpers ----------------
__device__ __forceinline__ u64 pk2(float lo, float hi) {
    u64 r;
    asm("mov.b64 %0,{%1,%2};" : "=l"(r) : "f"(lo), "f"(hi));
    return r;
}
__device__ __forceinline__ void upk2(float& lo, float& hi, u64 v) {
    asm("mov.b64 {%0,%1},%2;" : "=f"(lo), "=f"(hi) : "l"(v));
}
__device__ __forceinline__ u64 fma2(u64 a, u64 b, u64 c) {
    u64 d;
    asm("fma.rn.f32x2 %0,%1,%2,%3;" : "=l"(d) : "l"(a), "l"(b), "l"(c));
    return d;
}

// ---------------- tf32 mma helpers ----------------
__device__ __forceinline__ uint32_t tf32r(float f) {
    uint32_t r;
    asm("cvt.rna.tf32.f32 %0,%1;" : "=r"(r) : "f"(f));
    return r;
}
__device__ __forceinline__ float ex2(float x) {
    float r;
    asm("ex2.approx.f32 %0,%1;" : "=f"(r) : "f"(x));
    return r;
}
__device__ __forceinline__ void mma8(float* d, const uint32_t* a, uint32_t b0, uint32_t b1) {
    asm volatile(
        "mma.sync.aligned.m16n8k8.row.col.f32.tf32.tf32.f32 "
        "{%0,%1,%2,%3},{%4,%5,%6,%7},{%8,%9},{%0,%1,%2,%3};"
        : "+f"(d[0]), "+f"(d[1]), "+f"(d[2]), "+f"(d[3])
        : "r"(a[0]), "r"(a[1]), "r"(a[2]), "r"(a[3]), "r"(b0), "r"(b1));
}

// ---------------- SE: per-channel global mean ----------------
__global__ void mean_kernel(const float* __restrict__ high) {
    int bc = blockIdx.x;
    const float* p = high + (size_t)bc * NPIX;
    float s = 0.f;
    for (int i = threadIdx.x; i < NPIX; i += 256) s += p[i];
    __shared__ float red[256];
    red[threadIdx.x] = s; __syncthreads();
    for (int k = 128; k > 0; k >>= 1) {
        if (threadIdx.x < k) red[threadIdx.x] += red[threadIdx.x + k];
        __syncthreads();
    }
    if (threadIdx.x == 0) g_mean[bc] = red[0] * (1.f/NPIX);
}

// ---------------- SE: gate per (b,c) ----------------
__global__ void se_kernel(const float* __restrict__ w10, const float* __restrict__ w20,
                          const float* __restrict__ w11, const float* __restrict__ w21,
                          const float* __restrict__ w12, const float* __restrict__ w22) {
    int t = threadIdx.x;
    int b = t >> 6, c = t & 63;
    int g  = (c < 22) ? 0 : ((c < 43) ? 1 : 2);
    int of = (g == 0) ? 0 : ((g == 1) ? 22 : 43);
    int gc = (g == 0) ? 22 : 21;
    const float* w1 = (g==0) ? w10 : ((g==1) ? w11 : w12);
    const float* w2 = (g==0) ? w20 : ((g==1) ? w21 : w22);
    float h = 0.f;
    for (int j = 0; j < gc; j++) h += g_mean[b*64 + of + j] * w1[j];
    h = fmaxf(h, 0.f);
    float v = h * w2[c - of];
    g_sgate[t] = 1.f / (1.f + __expf(-v));
}

// ---------------- projections: 3 stages of 2 weights; 67KB smem -> 3 blocks/SM ----------------
#define WTS 68
#define QS 0.36067376022224085f
__global__ void __launch_bounds__(256,3) proj_kernel(
    const float* __restrict__ low, const float* __restrict__ high,
    const float* __restrict__ w_ql, const float* __restrict__ w_kh,
    const float* __restrict__ w_vh, const float* __restrict__ w_qh,
    const float* __restrict__ w_kl, const float* __restrict__ w_vl)
{
    extern __shared__ float sm[];
    float* xl = sm;            // 4096
    float* xh = sm + 4096;     // 4096
    float* wb = sm + 8192;     // 2 * 64*68 = 8704

    int t = threadIdx.x;
    int pix0 = blockIdx.x * 64;
    int b = blockIdx.y;

    for (int i4 = t; i4 < 1024; i4 += 256) {
        int c = i4 >> 4, pp = (i4 & 15) * 4;
        size_t gi = (size_t)(b*NC + c)*NPIX + pix0 + pp;
        float4 vl = *(const float4*)(low + gi);
        float4 vh = *(const float4*)(high + gi);
        float gt = g_sgate[b*64 + c];
        vh.x *= gt; vh.y *= gt; vh.z *= gt; vh.w *= gt;
        *(float4*)(xl + c*64 + pp) = vl;
        *(float4*)(xh + c*64 + pp) = vh;
    }

    int ot = (t >> 4) << 2;
    int nb = (t & 15) << 2;

    // s0: (0=ql[xl,QS], 4=kl[xl])   s1: (1=kh[xh], 2=vh[xh])   s2: (5=vl[xl], 3=qh[xh,QS])
    const float* WA[3]; const float* WB[3];
    WA[0] = w_ql; WB[0] = w_kl;
    WA[1] = w_kh; WB[1] = w_vh;
    WA[2] = w_vl; WB[2] = w_qh;
    const int slotA[3] = {0, 1, 5};
    const int slotB[3] = {4, 2, 3};

    for (int s = 0; s < 3; s++) {
        __syncthreads();
        bool scaleA = (s == 0), scaleB = (s == 2);
        for (int i = t; i < 8192; i += 256) {
            int p = i >> 12, j = i & 4095;
            int o = j >> 6, c = j & 63;
            float wv = (p == 0) ? WA[s][j] : WB[s][j];
            if ((p == 0 && scaleA) || (p == 1 && scaleB)) wv *= QS;
            wb[p*4352 + c*WTS + o] = wv;
        }
        __syncthreads();

        const float* XA = (s == 2) ? xl : ((s == 0) ? xl : xh);
        const float* XB = (s == 2) ? xh : ((s == 0) ? xl : xh);
        bool sameX = (s != 2);

        u64 acc2[2][4][2];
        #pragma unroll
        for (int p = 0; p < 2; p++)
            #pragma unroll
            for (int n = 0; n < 4; n++) { acc2[p][n][0] = 0ULL; acc2[p][n][1] = 0ULL; }

        if (sameX) {
            #pragma unroll 4
            for (int c = 0; c < 64; c++) {
                float4 x4 = *(const float4*)(XA + c*64 + nb);
                u64 xd0 = pk2(x4.x, x4.x);
                u64 xd1 = pk2(x4.y, x4.y);
                u64 xd2 = pk2(x4.z, x4.z);
                u64 xd3 = pk2(x4.w, x4.w);
                #pragma unroll
                for (int p = 0; p < 2; p++) {
                    ulonglong2 w2v = *(const ulonglong2*)(wb + p*4352 + c*WTS + ot);
                    acc2[p][0][0] = fma2(xd0, w2v.x, acc2[p][0][0]);
                    acc2[p][0][1] = fma2(xd0, w2v.y, acc2[p][0][1]);
                    acc2[p][1][0] = fma2(xd1, w2v.x, acc2[p][1][0]);
                    acc2[p][1][1] = fma2(xd1, w2v.y, acc2[p][1][1]);
                    acc2[p][2][0] = fma2(xd2, w2v.x, acc2[p][2][0]);
                    acc2[p][2][1] = fma2(xd2, w2v.y, acc2[p][2][1]);
                    acc2[p][3][0] = fma2(xd3, w2v.x, acc2[p][3][0]);
                    acc2[p][3][1] = fma2(xd3, w2v.y, acc2[p][3][1]);
                }
            }
        } else {
            #pragma unroll 4
            for (int c = 0; c < 64; c++) {
                float4 xa4 = *(const float4*)(XA + c*64 + nb);
                float4 xb4 = *(const float4*)(XB + c*64 + nb);
                u64 xa0 = pk2(xa4.x, xa4.x), xa1 = pk2(xa4.y, xa4.y);
                u64 xa2 = pk2(xa4.z, xa4.z), xa3 = pk2(xa4.w, xa4.w);
                u64 xb0 = pk2(xb4.x, xb4.x), xb1 = pk2(xb4.y, xb4.y);
                u64 xb2 = pk2(xb4.z, xb4.z), xb3 = pk2(xb4.w, xb4.w);
                ulonglong2 wa = *(const ulonglong2*)(wb + c*WTS + ot);
                ulonglong2 wv = *(const ulonglong2*)(wb + 4352 + c*WTS + ot);
                acc2[0][0][0] = fma2(xa0, wa.x, acc2[0][0][0]);
                acc2[0][0][1] = fma2(xa0, wa.y, acc2[0][0][1]);
                acc2[0][1][0] = fma2(xa1, wa.x, acc2[0][1][0]);
                acc2[0][1][1] = fma2(xa1, wa.y, acc2[0][1][1]);
                acc2[0][2][0] = fma2(xa2, wa.x, acc2[0][2][0]);
                acc2[0][2][1] = fma2(xa2, wa.y, acc2[0][2][1]);
                acc2[0][3][0] = fma2(xa3, wa.x, acc2[0][3][0]);
                acc2[0][3][1] = fma2(xa3, wa.y, acc2[0][3][1]);
                acc2[1][0][0] = fma2(xb0, wv.x, acc2[1][0][0]);
                acc2[1][0][1] = fma2(xb0, wv.y, acc2[1][0][1]);
                acc2[1][1][0] = fma2(xb1, wv.x, acc2[1][1][0]);
                acc2[1][1][1] = fma2(xb1, wv.y, acc2[1][1][1]);
                acc2[1][2][0] = fma2(xb2, wv.x, acc2[1][2][0]);
                acc2[1][2][1] = fma2(xb2, wv.y, acc2[1][2][1]);
                acc2[1][3][0] = fma2(xb3, wv.x, acc2[1][3][0]);
                acc2[1][3][1] = fma2(xb3, wv.y, acc2[1][3][1]);
            }
        }

        int sl[2]; sl[0] = slotA[s]; sl[1] = slotB[s];
        #pragma unroll
        for (int p = 0; p < 2; p++) {
            float lo0[4], hi0[4], lo1[4], hi1[4];
            #pragma unroll
            for (int n = 0; n < 4; n++) {
                upk2(lo0[n], hi0[n], acc2[p][n][0]);
                upk2(lo1[n], hi1[n], acc2[p][n][1]);
            }
            size_t base = (size_t)sl[p]*NB*NC*NPIX + (size_t)(b*NC)*NPIX + pix0 + nb;
            *(float4*)(g_proj + base + (size_t)(ot+0)*NPIX) = make_float4(lo0[0],lo0[1],lo0[2],lo0[3]);
            *(float4*)(g_proj + base + (size_t)(ot+1)*NPIX) = make_float4(hi0[0],hi0[1],hi0[2],hi0[3]);
            *(float4*)(g_proj + base + (size_t)(ot+2)*NPIX) = make_float4(lo1[0],lo1[1],lo1[2],lo1[3]);
            *(float4*)(g_proj + base + (size_t)(ot+3)*NPIX) = make_float4(hi1[0],hi1[1],hi1[2],hi1[3]);
        }
    }
}

// ---------------- attention: tf32 MMA v6 (m16 interleave, split accumulators) ----------------
#define KSTR 72
#define VSTR 68
#define KHSZ (16*KSTR)
#define VHSZ (16*VSTR)
#define SMEM_ATTN_WORDS (4*KHSZ + 4*VHSZ)

__global__ void __launch_bounds__(128, 5) attn_kernel()
{
    extern __shared__ uint32_t smu[];
    uint32_t* kbuf = smu;                      // 4*KHSZ
    uint32_t* vbuf = smu + 4*KHSZ;             // 4*VHSZ

    int t = threadIdx.x;
    int l = blockIdx.x, dir = blockIdx.y, b = blockIdx.z;
    int y0 = (l / NWIN) * 4, x0 = (l % NWIN) * 4;

    // stage + convert K and V (1-term tf32)
    for (int i4 = t; i4 < 2048; i4 += 128) {
        int p = i4 >> 10, rem = i4 & 1023;       // p: 0=k 1=v
        int slot = dir*3 + 1 + p;
        int c = rem >> 4, q4 = rem & 15;
        int r = q4 >> 1, cc = (q4 & 1) * 4;
        int n = r*8 + cc;
        int h = c >> 4, d = c & 15;
        size_t gi = ((size_t)slot*NB*NC + (size_t)(b*NC + c))*NPIX + (size_t)(y0 + r)*NW + x0 + cc;
        float4 v4 = *(const float4*)(g_proj + gi);
        uint4 e;
        e.x = tf32r(v4.x); e.y = tf32r(v4.y); e.z = tf32r(v4.z); e.w = tf32r(v4.w);
        uint32_t* dst = (p ? (vbuf + h*VHSZ + d*VSTR) : (kbuf + h*KHSZ + d*KSTR)) + n;
        *(uint4*)dst = e;
    }
    __syncthreads();

    int h = t >> 5, lane = t & 31;
    int gid = lane >> 2, tig = lane & 3;
    int sig = (gid & 1) ? ((gid >> 1) + 4) : (gid >> 1);   // sigma(gid)

    const uint32_t* kf = kbuf + h*KHSZ;
    const uint32_t* vf = vbuf + h*VHSZ;
    const float* Qg = g_proj + ((size_t)(dir ? 3 : 0)*NB*NC + (size_t)(b*NC + h*16))*NPIX;
    float* wdst = (dir ? g_win_h : g_win_l) + (size_t)(b*NL + l)*4096;  // [n][c]

    #pragma unroll
    for (int nt = 0; nt < 4; nt++) {
        int nbase = nt*16;
        size_t pA = (size_t)(y0 + 2*nt)*NW + x0 + gid;   // pixel for n = nbase+gid
        size_t pB = pA + NW;                              // pixel for n = nbase+gid+8

        // ---- Q A-fragments (1-term) from gmem, 2 d-chunks ----
        uint32_t qh[2][4];
        #pragma unroll
        for (int kq = 0; kq < 2; kq++) {
            int d0 = kq*8 + tig;
            qh[kq][0] = tf32r(Qg[(size_t)d0*NPIX     + pA]);
            qh[kq][1] = tf32r(Qg[(size_t)d0*NPIX     + pB]);
            qh[kq][2] = tf32r(Qg[(size_t)(d0+4)*NPIX + pA]);
            qh[kq][3] = tf32r(Qg[(size_t)(d0+4)*NPIX + pB]);
        }

        float o0a[4] = {0.f,0.f,0.f,0.f}, o0b[4] = {0.f,0.f,0.f,0.f};
        float o1a[4] = {0.f,0.f,0.f,0.f}, o1b[4] = {0.f,0.f,0.f,0.f};
        float rs0 = 0.f, rs1 = 0.f;

        #pragma unroll
        for (int m16 = 0; m16 < 64; m16 += 16) {
            // ---- two S tiles [n16 x m8] interleaved ----
            float ca[4] = {0.f,0.f,0.f,0.f};
            float cb[4] = {0.f,0.f,0.f,0.f};
            #pragma unroll
            for (int kq = 0; kq < 2; kq++) {
                const uint32_t* kr0 = kf + (kq*8+tig)*KSTR + sig;
                const uint32_t* kr1 = kf + (kq*8+tig+4)*KSTR + sig;
                uint32_t ka0 = kr0[m16],   ka1 = kr1[m16];
                uint32_t kb0 = kr0[m16+8], kb1 = kr1[m16+8];
                mma8(ca, qh[kq], ka0, ka1);
                mma8(cb, qh[kq], kb0, kb1);
            }
            // ---- exp, rowsum, P 1-term (both chunks) ----
            float ea0 = ex2(ca[0]), ea1 = ex2(ca[1]), ea2 = ex2(ca[2]), ea3 = ex2(ca[3]);
            float eb0 = ex2(cb[0]), eb1 = ex2(cb[1]), eb2 = ex2(cb[2]), eb3 = ex2(cb[3]);
            rs0 += (ea0 + ea1) + (eb0 + eb1);
            rs1 += (ea2 + ea3) + (eb2 + eb3);
            uint32_t pa0 = tf32r(ea0), pa1 = tf32r(ea1), pa2 = tf32r(ea2), pa3 = tf32r(ea3);
            uint32_t pb0 = tf32r(eb0), pb1 = tf32r(eb1), pb2 = tf32r(eb2), pb3 = tf32r(eb3);
            // ---- V A-fragments (pre-converted), both chunks ----
            uint32_t va[4], vb[4];
            va[0] = vf[gid*VSTR     + m16 + tig    ];
            va[1] = vf[(gid+8)*VSTR + m16 + tig    ];
            va[2] = vf[gid*VSTR     + m16 + tig + 4];
            va[3] = vf[(gid+8)*VSTR + m16 + tig + 4];
            vb[0] = vf[gid*VSTR     + m16 + 8 + tig    ];
            vb[1] = vf[(gid+8)*VSTR + m16 + 8 + tig    ];
            vb[2] = vf[gid*VSTR     + m16 + 8 + tig + 4];
            vb[3] = vf[(gid+8)*VSTR + m16 + 8 + tig + 4];
            // ---- AV into split accumulators (independent chains) ----
            mma8(o0a, va, pa0, pa1);
            mma8(o1a, va, pa2, pa3);
            mma8(o0b, vb, pb0, pb1);
            mma8(o1b, vb, pb2, pb3);
        }
        // ---- full rowsums (reduce across tig) ----
        rs0 += __shfl_xor_sync(0xffffffffu, rs0, 1);
        rs0 += __shfl_xor_sync(0xffffffffu, rs0, 2);
        rs1 += __shfl_xor_sync(0xffffffffu, rs1, 1);
        rs1 += __shfl_xor_sync(0xffffffffu, rs1, 2);
        // rowsum for n = nbase+j lives as rs0 (j<8) / rs1 (j>=8) in lanes of quad j
        float sA0 = __shfl_sync(0xffffffffu, rs0, 8*tig);       // n = 2tig
        float sA1 = __shfl_sync(0xffffffffu, rs0, 8*tig + 4);   // n = 2tig+1
        float sB0 = __shfl_sync(0xffffffffu, rs1, 8*tig);       // n = 8+2tig
        float sB1 = __shfl_sync(0xffffffffu, rs1, 8*tig + 4);   // n = 9+2tig
        float iA0 = 1.f / sA0, iA1 = 1.f / sA1;
        float iB0 = 1.f / sB0, iB1 = 1.f / sB1;
        // ---- combine split accumulators, normalize, per-window store ----
        {
            int n0 = nbase + 2*tig;
            float* w0 = wdst + (size_t)n0*64 + h*16;
            w0[gid]          = (o0a[0] + o0b[0]) * iA0;
            w0[64 + gid]     = (o0a[1] + o0b[1]) * iA1;
            w0[gid + 8]      = (o0a[2] + o0b[2]) * iA0;
            w0[64 + gid + 8] = (o0a[3] + o0b[3]) * iA1;
            float* w1 = wdst + (size_t)(n0+8)*64 + h*16;
            w1[gid]          = (o1a[0] + o1b[0]) * iB0;
            w1[64 + gid]     = (o1a[1] + o1b[1]) * iB1;
            w1[gid + 8]      = (o1a[2] + o1b[2]) * iB0;
            w1[64 + gid + 8] = (o1a[3] + o1b[3]) * iB1;
        }
    }
}

// ---------------- epilogue: gather <=4 windows per pixel, 1x1 proj + residual ----------------
__global__ void __launch_bounds__(256) epi_kernel(
    const float* __restrict__ low, const float* __restrict__ high,
    const float* __restrict__ wpl, const float* __restrict__ wph,
    float* __restrict__ out)
{
    extern __shared__ float sm[];
    float* tl = sm;                  // 64*65 = 4160
    float* th = sm + 4160;           // 4160
    float* wl = sm + 8320;           // 64*68 = 4352
    float* wh = sm + 8320 + 4352;    // 4352 (total 17024 floats)

    int t = threadIdx.x;
    int chunk = blockIdx.x;          // 1024 chunks: 256 per batch, 64 px each
    int b = chunk >> 8;
    int pix0 = (chunk & 255) * 64;

    for (int i = t; i < 4096; i += 256) {
        int o = i >> 6, c = i & 63;
        wl[c*WTS + o] = wpl[i];
        wh[c*WTS + o] = wph[i];
    }

    int cid = t & 63, pg = t >> 6;
    for (int it = 0; it < 16; it++) {
        int px = it*4 + pg;
        int pix = pix0 + px;
        int y = pix >> 7, x = pix & 127;
        int iyl = (y >= 8) ? ((y - 4) >> 2) : 0;
        int iyh = y >> 2; if (iyh > 30) iyh = 30;
        int ixl = (x >= 8) ? ((x - 4) >> 2) : 0;
        int ixh = x >> 2; if (ixh > 30) ixh = 30;
        float sl = 0.f, sh = 0.f;
        for (int iy = iyl; iy <= iyh; iy++) {
            for (int ix = ixl; ix <= ixh; ix++) {
                int ll = iy*NWIN + ix;
                int n = (y - 4*iy)*8 + (x - 4*ix);
                size_t base = ((size_t)(b*NL + ll)*64 + n)*64 + cid;
                sl += g_win_l[base];
                sh += g_win_h[base];
            }
        }
        float ic = 1.f / (float)((iyh - iyl + 1) * (ixh - ixl + 1));
        tl[cid*65 + px] = sl * ic;
        th[cid*65 + px] = sh * ic;
    }
    __syncthreads();

    int px = t & 63, og = (t >> 6) * 16;
    u64 rl2[8], rh2[8];
    #pragma unroll
    for (int j = 0; j < 8; j++) { rl2[j] = 0ULL; rh2[j] = 0ULL; }

    #pragma unroll 4
    for (int c = 0; c < 64; c++) {
        float tv = tl[c*65 + px];
        float hv = th[c*65 + px];
        u64 tv2 = pk2(tv, tv);
        u64 hv2 = pk2(hv, hv);
        const ulonglong2* wlr = (const ulonglong2*)(wl + c*WTS + og);
        const ulonglong2* whr = (const ulonglong2*)(wh + c*WTS + og);
        #pragma unroll
        for (int o4 = 0; o4 < 4; o4++) {
            ulonglong2 a2 = wlr[o4];
            ulonglong2 b2 = whr[o4];
            rl2[o4*2]   = fma2(tv2, a2.x, rl2[o4*2]);
            rl2[o4*2+1] = fma2(tv2, a2.y, rl2[o4*2+1]);
            rh2[o4*2]   = fma2(hv2, b2.x, rh2[o4*2]);
            rh2[o4*2+1] = fma2(hv2, b2.y, rh2[o4*2+1]);
        }
    }
    size_t half = (size_t)NB*NC*NPIX;
    int pix = pix0 + px;
    #pragma unroll
    for (int j = 0; j < 8; j++) {
        float a, bb; upk2(a, bb, rl2[j]);
        float c2, d2; upk2(c2, d2, rh2[j]);
        int o0 = og + j*2;
        size_t gi0 = (size_t)(b*NC + o0)*NPIX + pix;
        size_t gi1 = (size_t)(b*NC + o0 + 1)*NPIX + pix;
        out[gi0]        = low[gi0]  + a;
        out[gi1]        = low[gi1]  + bb;
        out[half + gi0] = high[gi0] + c2;
        out[half + gi1] = high[gi1] + d2;
    }
}

extern "C" void kernel_launch(void* const* d_in, const int* in_sizes, int n_in,
                              void* d_out, int out_size)
{
    (void)in_sizes; (void)n_in; (void)out_size;
    const float* low  = (const float*)d_in[0];
    const float* high = (const float*)d_in[1];
    const float* w_ql = (const float*)d_in[2];
    const float* w_kh = (const float*)d_in[3];
    const float* w_vh = (const float*)d_in[4];
    const float* w_qh = (const float*)d_in[5];
    const float* w_kl = (const float*)d_in[6];
    const float* w_vl = (const float*)d_in[7];
    const float* wpl  = (const float*)d_in[8];
    const float* wph  = (const float*)d_in[9];

    int proj_smem = (8192 + 8704) * 4;        // 67.6 KB
    int attn_smem = SMEM_ATTN_WORDS * 4;      // 35.8 KB
    int epi_smem  = 17024 * 4;                // 66.5 KB

    cudaFuncSetAttribute(proj_kernel, cudaFuncAttributeMaxDynamicSharedMemorySize, proj_smem);
    cudaFuncSetAttribute(attn_kernel, cudaFuncAttributeMaxDynamicSharedMemorySize, attn_smem);
    cudaFuncSetAttribute(epi_kernel,  cudaFuncAttributeMaxDynamicSharedMemorySize, epi_smem);

    mean_kernel<<<NB*NC, 256>>>(high);
    se_kernel<<<1, 256>>>((const float*)d_in[10], (const float*)d_in[11],
                          (const float*)d_in[12], (const float*)d_in[13],
                          (const float*)d_in[14], (const float*)d_in[15]);
    proj_kernel<<<dim3(NPIX/64, NB), 256, proj_smem>>>(low, high, w_ql, w_kh, w_vh, w_qh, w_kl, w_vl);
    attn_kernel<<<dim3(NL, 2, NB), 128, attn_smem>>>();
    epi_kernel<<<1024, 256, epi_smem>>>(low, high, wpl, wph, (float*)d_out);
}

// round 15
// speedup vs baseline: 1.1399x; 1.1346x over previous
#include <cuda_runtime.h>
#include <cstdint>

#define NB 4
#define NC 64
#define NH 128
#define NW 128
#define NPIX (NH*NW)
#define NWIN 31
#define NL (NWIN*NWIN)

typedef unsigned long long u64;

// proj slot order: 0=ql 1=kh 2=vh 3=qh 4=kl 5=vl  (dir0 uses 0,1,2; dir1 uses 3,4,5)
__device__ float g_proj[6*NB*NC*NPIX];
__device__ float g_win_l[(size_t)NB*NL*64*64];   // [b][l][n][c] per-window outputs
__device__ float g_win_h[(size_t)NB*NL*64*64];
__device__ float g_mean[NB*NC];
__device__ float g_sgate[NB*NC];

// ---------------- packed f32x2 helpers ----------------
__device__ __forceinline__ u64 pk2(float lo, float hi) {
    u64 r;
    asm("mov.b64 %0,{%1,%2};" : "=l"(r) : "f"(lo), "f"(hi));
    return r;
}
__device__ __forceinline__ void upk2(float& lo, float& hi, u64 v) {
    asm("mov.b64 {%0,%1},%2;" : "=f"(lo), "=f"(hi) : "l"(v));
}
__device__ __forceinline__ u64 fma2(u64 a, u64 b, u64 c) {
    u64 d;
    asm("fma.rn.f32x2 %0,%1,%2,%3;" : "=l"(d) : "l"(a), "l"(b), "l"(c));
    return d;
}

// ---------------- tf32 mma helpers ----------------
__device__ __forceinline__ uint32_t tf32r(float f) {
    uint32_t r;
    asm("cvt.rna.tf32.f32 %0,%1;" : "=r"(r) : "f"(f));
    return r;
}
__device__ __forceinline__ float ex2(float x) {
    float r;
    asm("ex2.approx.f32 %0,%1;" : "=f"(r) : "f"(x));
    return r;
}
__device__ __forceinline__ void mma8(float* d, const uint32_t* a, uint32_t b0, uint32_t b1) {
    asm volatile(
        "mma.sync.aligned.m16n8k8.row.col.f32.tf32.tf32.f32 "
        "{%0,%1,%2,%3},{%4,%5,%6,%7},{%8,%9},{%0,%1,%2,%3};"
        : "+f"(d[0]), "+f"(d[1]), "+f"(d[2]), "+f"(d[3])
        : "r"(a[0]), "r"(a[1]), "r"(a[2]), "r"(a[3]), "r"(b0), "r"(b1));
}

// ---------------- SE: per-channel global mean ----------------
__global__ void mean_kernel(const float* __restrict__ high) {
    int bc = blockIdx.x;
    const float* p = high + (size_t)bc * NPIX;
    float s = 0.f;
    for (int i = threadIdx.x; i < NPIX; i += 256) s += p[i];
    __shared__ float red[256];
    red[threadIdx.x] = s; __syncthreads();
    for (int k = 128; k > 0; k >>= 1) {
        if (threadIdx.x < k) red[threadIdx.x] += red[threadIdx.x + k];
        __syncthreads();
    }
    if (threadIdx.x == 0) g_mean[bc] = red[0] * (1.f/NPIX);
}

// ---------------- SE: gate per (b,c) ----------------
__global__ void se_kernel(const float* __restrict__ w10, const float* __restrict__ w20,
                          const float* __restrict__ w11, const float* __restrict__ w21,
                          const float* __restrict__ w12, const float* __restrict__ w22) {
    int t = threadIdx.x;
    int b = t >> 6, c = t & 63;
    int g  = (c < 22) ? 0 : ((c < 43) ? 1 : 2);
    int of = (g == 0) ? 0 : ((g == 1) ? 22 : 43);
    int gc = (g == 0) ? 22 : 21;
    const float* w1 = (g==0) ? w10 : ((g==1) ? w11 : w12);
    const float* w2 = (g==0) ? w20 : ((g==1) ? w21 : w22);
    float h = 0.f;
    for (int j = 0; j < gc; j++) h += g_mean[b*64 + of + j] * w1[j];
    h = fmaxf(h, 0.f);
    float v = h * w2[c - of];
    g_sgate[t] = 1.f / (1.f + __expf(-v));
}

// ---------------- projections: 3 stages of 2 weights; 67KB smem -> 3 blocks/SM ----------------
#define WTS 68
#define QS 0.36067376022224085f
__global__ void __launch_bounds__(256,3) proj_kernel(
    const float* __restrict__ low, const float* __restrict__ high,
    const float* __restrict__ w_ql, const float* __restrict__ w_kh,
    const float* __restrict__ w_vh, const float* __restrict__ w_qh,
    const float* __restrict__ w_kl, const float* __restrict__ w_vl)
{
    extern __shared__ float sm[];
    float* xl = sm;            // 4096
    float* xh = sm + 4096;     // 4096
    float* wb = sm + 8192;     // 2 * 64*68 = 8704

    int t = threadIdx.x;
    int pix0 = blockIdx.x * 64;
    int b = blockIdx.y;

    for (int i4 = t; i4 < 1024; i4 += 256) {
        int c = i4 >> 4, pp = (i4 & 15) * 4;
        size_t gi = (size_t)(b*NC + c)*NPIX + pix0 + pp;
        float4 vl = *(const float4*)(low + gi);
        float4 vh = *(const float4*)(high + gi);
        float gt = g_sgate[b*64 + c];
        vh.x *= gt; vh.y *= gt; vh.z *= gt; vh.w *= gt;
        *(float4*)(xl + c*64 + pp) = vl;
        *(float4*)(xh + c*64 + pp) = vh;
    }

    int ot = (t >> 4) << 2;
    int nb = (t & 15) << 2;

    // s0: (0=ql[xl,QS], 4=kl[xl])   s1: (1=kh[xh], 2=vh[xh])   s2: (5=vl[xl], 3=qh[xh,QS])
    const float* WA[3]; const float* WB[3];
    WA[0] = w_ql; WB[0] = w_kl;
    WA[1] = w_kh; WB[1] = w_vh;
    WA[2] = w_vl; WB[2] = w_qh;
    const int slotA[3] = {0, 1, 5};
    const int slotB[3] = {4, 2, 3};

    for (int s = 0; s < 3; s++) {
        __syncthreads();
        bool scaleA = (s == 0), scaleB = (s == 2);
        for (int i = t; i < 8192; i += 256) {
            int p = i >> 12, j = i & 4095;
            int o = j >> 6, c = j & 63;
            float wv = (p == 0) ? WA[s][j] : WB[s][j];
            if ((p == 0 && scaleA) || (p == 1 && scaleB)) wv *= QS;
            wb[p*4352 + c*WTS + o] = wv;
        }
        __syncthreads();

        const float* XA = (s == 2) ? xl : ((s == 0) ? xl : xh);
        const float* XB = (s == 2) ? xh : ((s == 0) ? xl : xh);
        bool sameX = (s != 2);

        u64 acc2[2][4][2];
        #pragma unroll
        for (int p = 0; p < 2; p++)
            #pragma unroll
            for (int n = 0; n < 4; n++) { acc2[p][n][0] = 0ULL; acc2[p][n][1] = 0ULL; }

        if (sameX) {
            #pragma unroll 4
            for (int c = 0; c < 64; c++) {
                float4 x4 = *(const float4*)(XA + c*64 + nb);
                u64 xd0 = pk2(x4.x, x4.x);
                u64 xd1 = pk2(x4.y, x4.y);
                u64 xd2 = pk2(x4.z, x4.z);
                u64 xd3 = pk2(x4.w, x4.w);
                #pragma unroll
                for (int p = 0; p < 2; p++) {
                    ulonglong2 w2v = *(const ulonglong2*)(wb + p*4352 + c*WTS + ot);
                    acc2[p][0][0] = fma2(xd0, w2v.x, acc2[p][0][0]);
                    acc2[p][0][1] = fma2(xd0, w2v.y, acc2[p][0][1]);
                    acc2[p][1][0] = fma2(xd1, w2v.x, acc2[p][1][0]);
                    acc2[p][1][1] = fma2(xd1, w2v.y, acc2[p][1][1]);
                    acc2[p][2][0] = fma2(xd2, w2v.x, acc2[p][2][0]);
                    acc2[p][2][1] = fma2(xd2, w2v.y, acc2[p][2][1]);
                    acc2[p][3][0] = fma2(xd3, w2v.x, acc2[p][3][0]);
                    acc2[p][3][1] = fma2(xd3, w2v.y, acc2[p][3][1]);
                }
            }
        } else {
            #pragma unroll 4
            for (int c = 0; c < 64; c++) {
                float4 xa4 = *(const float4*)(XA + c*64 + nb);
                float4 xb4 = *(const float4*)(XB + c*64 + nb);
                u64 xa0 = pk2(xa4.x, xa4.x), xa1 = pk2(xa4.y, xa4.y);
                u64 xa2 = pk2(xa4.z, xa4.z), xa3 = pk2(xa4.w, xa4.w);
                u64 xb0 = pk2(xb4.x, xb4.x), xb1 = pk2(xb4.y, xb4.y);
                u64 xb2 = pk2(xb4.z, xb4.z), xb3 = pk2(xb4.w, xb4.w);
                ulonglong2 wa = *(const ulonglong2*)(wb + c*WTS + ot);
                ulonglong2 wv = *(const ulonglong2*)(wb + 4352 + c*WTS + ot);
                acc2[0][0][0] = fma2(xa0, wa.x, acc2[0][0][0]);
                acc2[0][0][1] = fma2(xa0, wa.y, acc2[0][0][1]);
                acc2[0][1][0] = fma2(xa1, wa.x, acc2[0][1][0]);
                acc2[0][1][1] = fma2(xa1, wa.y, acc2[0][1][1]);
                acc2[0][2][0] = fma2(xa2, wa.x, acc2[0][2][0]);
                acc2[0][2][1] = fma2(xa2, wa.y, acc2[0][2][1]);
                acc2[0][3][0] = fma2(xa3, wa.x, acc2[0][3][0]);
                acc2[0][3][1] = fma2(xa3, wa.y, acc2[0][3][1]);
                acc2[1][0][0] = fma2(xb0, wv.x, acc2[1][0][0]);
                acc2[1][0][1] = fma2(xb0, wv.y, acc2[1][0][1]);
                acc2[1][1][0] = fma2(xb1, wv.x, acc2[1][1][0]);
                acc2[1][1][1] = fma2(xb1, wv.y, acc2[1][1][1]);
                acc2[1][2][0] = fma2(xb2, wv.x, acc2[1][2][0]);
                acc2[1][2][1] = fma2(xb2, wv.y, acc2[1][2][1]);
                acc2[1][3][0] = fma2(xb3, wv.x, acc2[1][3][0]);
                acc2[1][3][1] = fma2(xb3, wv.y, acc2[1][3][1]);
            }
        }

        int sl[2]; sl[0] = slotA[s]; sl[1] = slotB[s];
        #pragma unroll
        for (int p = 0; p < 2; p++) {
            float lo0[4], hi0[4], lo1[4], hi1[4];
            #pragma unroll
            for (int n = 0; n < 4; n++) {
                upk2(lo0[n], hi0[n], acc2[p][n][0]);
                upk2(lo1[n], hi1[n], acc2[p][n][1]);
            }
            size_t base = (size_t)sl[p]*NB*NC*NPIX + (size_t)(b*NC)*NPIX + pix0 + nb;
            *(float4*)(g_proj + base + (size_t)(ot+0)*NPIX) = make_float4(lo0[0],lo0[1],lo0[2],lo0[3]);
            *(float4*)(g_proj + base + (size_t)(ot+1)*NPIX) = make_float4(hi0[0],hi0[1],hi0[2],hi0[3]);
            *(float4*)(g_proj + base + (size_t)(ot+2)*NPIX) = make_float4(lo1[0],lo1[1],lo1[2],lo1[3]);
            *(float4*)(g_proj + base + (size_t)(ot+3)*NPIX) = make_float4(hi1[0],hi1[1],hi1[2],hi1[3]);
        }
    }
}

// ---------------- attention: tf32 MMA v4 (all 1-term, STG fold) — R12 exact ----------------
#define KSTR 72
#define VSTR 68
#define KHSZ (16*KSTR)
#define VHSZ (16*VSTR)
#define SMEM_ATTN_WORDS (4*KHSZ + 4*VHSZ + 256)

__global__ void __launch_bounds__(128, 5) attn_kernel()
{
    extern __shared__ uint32_t smu[];
    uint32_t* kbuf = smu;                      // 4*KHSZ
    uint32_t* vbuf = smu + 4*KHSZ;             // 4*VHSZ
    float*    sinv = (float*)(smu + 4*KHSZ + 4*VHSZ);   // 256

    int t = threadIdx.x;
    int l = blockIdx.x, dir = blockIdx.y, b = blockIdx.z;
    int y0 = (l / NWIN) * 4, x0 = (l % NWIN) * 4;

    // stage + convert K and V (1-term tf32)
    for (int i4 = t; i4 < 2048; i4 += 128) {
        int p = i4 >> 10, rem = i4 & 1023;       // p: 0=k 1=v
        int slot = dir*3 + 1 + p;
        int c = rem >> 4, q4 = rem & 15;
        int r = q4 >> 1, cc = (q4 & 1) * 4;
        int n = r*8 + cc;
        int h = c >> 4, d = c & 15;
        size_t gi = ((size_t)slot*NB*NC + (size_t)(b*NC + c))*NPIX + (size_t)(y0 + r)*NW + x0 + cc;
        float4 v4 = *(const float4*)(g_proj + gi);
        uint4 e;
        e.x = tf32r(v4.x); e.y = tf32r(v4.y); e.z = tf32r(v4.z); e.w = tf32r(v4.w);
        uint32_t* dst = (p ? (vbuf + h*VHSZ + d*VSTR) : (kbuf + h*KHSZ + d*KSTR)) + n;
        *(uint4*)dst = e;
    }
    __syncthreads();

    int h = t >> 5, lane = t & 31;
    int gid = lane >> 2, tig = lane & 3;
    int sig = (gid & 1) ? ((gid >> 1) + 4) : (gid >> 1);   // sigma(gid)

    const uint32_t* kf = kbuf + h*KHSZ;
    const uint32_t* vf = vbuf + h*VHSZ;
    const float* Qg = g_proj + ((size_t)(dir ? 3 : 0)*NB*NC + (size_t)(b*NC + h*16))*NPIX;
    float* wdst = (dir ? g_win_h : g_win_l) + (size_t)(b*NL + l)*4096;  // [n][c]

    #pragma unroll
    for (int nt = 0; nt < 4; nt++) {
        int nbase = nt*16;
        size_t pA = (size_t)(y0 + 2*nt)*NW + x0 + gid;   // pixel for n = nbase+gid
        size_t pB = pA + NW;                              // pixel for n = nbase+gid+8

        // ---- Q A-fragments (1-term) from gmem, 2 d-chunks ----
        uint32_t qh[2][4];
        #pragma unroll
        for (int kq = 0; kq < 2; kq++) {
            int d0 = kq*8 + tig;
            qh[kq][0] = tf32r(Qg[(size_t)d0*NPIX     + pA]);
            qh[kq][1] = tf32r(Qg[(size_t)d0*NPIX     + pB]);
            qh[kq][2] = tf32r(Qg[(size_t)(d0+4)*NPIX + pA]);
            qh[kq][3] = tf32r(Qg[(size_t)(d0+4)*NPIX + pB]);
        }

        float o0[4] = {0.f,0.f,0.f,0.f};   // O tile, n = nbase + 0..7
        float o1[4] = {0.f,0.f,0.f,0.f};   // O tile, n = nbase + 8..15
        float rs0 = 0.f, rs1 = 0.f;

        #pragma unroll
        for (int m8 = 0; m8 < 64; m8 += 8) {
            // ---- S tile [n16 x m8]: 2 MMA ----
            float c[4] = {0.f,0.f,0.f,0.f};
            #pragma unroll
            for (int kq = 0; kq < 2; kq++) {
                uint32_t kk0 = kf[(kq*8+tig)*KSTR   + m8 + sig];
                uint32_t kk1 = kf[(kq*8+tig+4)*KSTR + m8 + sig];
                mma8(c, qh[kq], kk0, kk1);
            }
            // ---- exp, rowsum, P 1-term ----
            float e0 = ex2(c[0]), e1 = ex2(c[1]), e2 = ex2(c[2]), e3 = ex2(c[3]);
            rs0 += e0 + e1;
            rs1 += e2 + e3;
            uint32_t p0 = tf32r(e0), p1 = tf32r(e1), p2 = tf32r(e2), p3 = tf32r(e3);
            // ---- V A-fragments (1-term, pre-converted) ----
            uint32_t va[4];
            va[0] = vf[gid*VSTR     + m8 + tig    ];
            va[1] = vf[(gid+8)*VSTR + m8 + tig    ];
            va[2] = vf[gid*VSTR     + m8 + tig + 4];
            va[3] = vf[(gid+8)*VSTR + m8 + tig + 4];
            // ---- AV: 2 MMA ----
            mma8(o0, va, p0, p1);
            mma8(o1, va, p2, p3);
        }
        // ---- softmax denominators: reduce across the 4 tig lanes ----
        rs0 += __shfl_xor_sync(0xffffffffu, rs0, 1);
        rs0 += __shfl_xor_sync(0xffffffffu, rs0, 2);
        rs1 += __shfl_xor_sync(0xffffffffu, rs1, 1);
        rs1 += __shfl_xor_sync(0xffffffffu, rs1, 2);
        if (tig == 0) {
            sinv[h*64 + nbase + gid]     = 1.f / rs0;
            sinv[h*64 + nbase + gid + 8] = 1.f / rs1;
        }
        __syncwarp();
        // ---- normalize + per-window store (no atomics) ----
        #pragma unroll
        for (int jt = 0; jt < 2; jt++) {
            const float* ot = jt ? o1 : o0;
            int n0 = nbase + jt*8 + 2*tig;
            float inv0 = sinv[h*64 + n0];
            float inv1 = sinv[h*64 + n0 + 1];
            float* w0 = wdst + (size_t)n0*64 + h*16;
            w0[gid]          = ot[0]*inv0;
            w0[64 + gid]     = ot[1]*inv1;
            w0[gid + 8]      = ot[2]*inv0;
            w0[64 + gid + 8] = ot[3]*inv1;
        }
    }
}

// ---------------- epilogue: vectorized gather (LDG.128), 1x1 proj + residual ----------------
__global__ void __launch_bounds__(256) epi_kernel(
    const float* __restrict__ low, const float* __restrict__ high,
    const float* __restrict__ wpl, const float* __restrict__ wph,
    float* __restrict__ out)
{
    extern __shared__ float sm[];
    float* tl = sm;                  // 64*65 = 4160
    float* th = sm + 4160;           // 4160
    float* wl = sm + 8320;           // 64*68 = 4352
    float* wh = sm + 8320 + 4352;    // 4352 (total 17024 floats)

    int t = threadIdx.x;
    int chunk = blockIdx.x;          // 1024 chunks: 256 per batch, 64 px each
    int b = chunk >> 8;
    int pix0 = (chunk & 255) * 64;

    for (int i = t; i < 4096; i += 256) {
        int o = i >> 6, c = i & 63;
        wl[c*WTS + o] = wpl[i];
        wh[c*WTS + o] = wph[i];
    }

    // gather: 16 threads per pixel, 4 channels per thread (float4)
    int cg = (t & 15) * 4;           // channel group base
    int pxg = t >> 4;                // 0..15
    for (int it = 0; it < 4; it++) {
        int px = it*16 + pxg;
        int pix = pix0 + px;
        int y = pix >> 7, x = pix & 127;
        int iyl = (y >= 8) ? ((y - 4) >> 2) : 0;
        int iyh = y >> 2; if (iyh > 30) iyh = 30;
        int ixl = (x >= 8) ? ((x - 4) >> 2) : 0;
        int ixh = x >> 2; if (ixh > 30) ixh = 30;
        float4 sl = make_float4(0.f,0.f,0.f,0.f);
        float4 sh = make_float4(0.f,0.f,0.f,0.f);
        for (int iy = iyl; iy <= iyh; iy++) {
            for (int ix = ixl; ix <= ixh; ix++) {
                int ll = iy*NWIN + ix;
                int n = (y - 4*iy)*8 + (x - 4*ix);
                size_t base = ((size_t)(b*NL + ll)*64 + n)*64 + cg;
                float4 a = *(const float4*)(g_win_l + base);
                float4 bb = *(const float4*)(g_win_h + base);
                sl.x += a.x;  sl.y += a.y;  sl.z += a.z;  sl.w += a.w;
                sh.x += bb.x; sh.y += bb.y; sh.z += bb.z; sh.w += bb.w;
            }
        }
        float ic = 1.f / (float)((iyh - iyl + 1) * (ixh - ixl + 1));
        tl[(cg+0)*65 + px] = sl.x * ic;
        tl[(cg+1)*65 + px] = sl.y * ic;
        tl[(cg+2)*65 + px] = sl.z * ic;
        tl[(cg+3)*65 + px] = sl.w * ic;
        th[(cg+0)*65 + px] = sh.x * ic;
        th[(cg+1)*65 + px] = sh.y * ic;
        th[(cg+2)*65 + px] = sh.z * ic;
        th[(cg+3)*65 + px] = sh.w * ic;
    }
    __syncthreads();

    int px = t & 63, og = (t >> 6) * 16;
    u64 rl2[8], rh2[8];
    #pragma unroll
    for (int j = 0; j < 8; j++) { rl2[j] = 0ULL; rh2[j] = 0ULL; }

    #pragma unroll 4
    for (int c = 0; c < 64; c++) {
        float tv = tl[c*65 + px];
        float hv = th[c*65 + px];
        u64 tv2 = pk2(tv, tv);
        u64 hv2 = pk2(hv, hv);
        const ulonglong2* wlr = (const ulonglong2*)(wl + c*WTS + og);
        const ulonglong2* whr = (const ulonglong2*)(wh + c*WTS + og);
        #pragma unroll
        for (int o4 = 0; o4 < 4; o4++) {
            ulonglong2 a2 = wlr[o4];
            ulonglong2 b2 = whr[o4];
            rl2[o4*2]   = fma2(tv2, a2.x, rl2[o4*2]);
            rl2[o4*2+1] = fma2(tv2, a2.y, rl2[o4*2+1]);
            rh2[o4*2]   = fma2(hv2, b2.x, rh2[o4*2]);
            rh2[o4*2+1] = fma2(hv2, b2.y, rh2[o4*2+1]);
        }
    }
    size_t half = (size_t)NB*NC*NPIX;
    int pix = pix0 + px;
    #pragma unroll
    for (int j = 0; j < 8; j++) {
        float a, bb; upk2(a, bb, rl2[j]);
        float c2, d2; upk2(c2, d2, rh2[j]);
        int o0 = og + j*2;
        size_t gi0 = (size_t)(b*NC + o0)*NPIX + pix;
        size_t gi1 = (size_t)(b*NC + o0 + 1)*NPIX + pix;
        out[gi0]        = low[gi0]  + a;
        out[gi1]        = low[gi1]  + bb;
        out[half + gi0] = high[gi0] + c2;
        out[half + gi1] = high[gi1] + d2;
    }
}

extern "C" void kernel_launch(void* const* d_in, const int* in_sizes, int n_in,
                              void* d_out, int out_size)
{
    (void)in_sizes; (void)n_in; (void)out_size;
    const float* low  = (const float*)d_in[0];
    const float* high = (const float*)d_in[1];
    const float* w_ql = (const float*)d_in[2];
    const float* w_kh = (const float*)d_in[3];
    const float* w_vh = (const float*)d_in[4];
    const float* w_qh = (const float*)d_in[5];
    const float* w_kl = (const float*)d_in[6];
    const float* w_vl = (const float*)d_in[7];
    const float* wpl  = (const float*)d_in[8];
    const float* wph  = (const float*)d_in[9];

    int proj_smem = (8192 + 8704) * 4;        // 67.6 KB
    int attn_smem = SMEM_ATTN_WORDS * 4;      // ~36.9 KB
    int epi_smem  = 17024 * 4;                // 66.5 KB

    cudaFuncSetAttribute(proj_kernel, cudaFuncAttributeMaxDynamicSharedMemorySize, proj_smem);
    cudaFuncSetAttribute(attn_kernel, cudaFuncAttributeMaxDynamicSharedMemorySize, attn_smem);
    cudaFuncSetAttribute(epi_kernel,  cudaFuncAttributeMaxDynamicSharedMemorySize, epi_smem);

    mean_kernel<<<NB*NC, 256>>>(high);
    se_kernel<<<1, 256>>>((const float*)d_in[10], (const float*)d_in[11],
                          (const float*)d_in[12], (const float*)d_in[13],
                          (const float*)d_in[14], (const float*)d_in[15]);
    proj_kernel<<<dim3(NPIX/64, NB), 256, proj_smem>>>(low, high, w_ql, w_kh, w_vh, w_qh, w_kl, w_vl);
    attn_kernel<<<dim3(NL, 2, NB), 128, attn_smem>>>();
    epi_kernel<<<1024, 256, epi_smem>>>(low, high, wpl, wph, (float*)d_out);
}

// round 16
// speedup vs baseline: 1.3192x; 1.1572x over previous
#include <cuda_runtime.h>
#include <cuda_fp16.h>
#include <cstdint>

#define NB 4
#define NC 64
#define NH 128
#define NW 128
#define NPIX (NH*NW)
#define NWIN 31
#define NL (NWIN*NWIN)

typedef unsigned long long u64;

// proj slot order: 0=ql 1=kh 2=vh 3=qh 4=kl 5=vl  (dir0 uses 0,1,2; dir1 uses 3,4,5)
// Stored fp16: same 10-bit mantissa as the tf32 rounding attn applies anyway.
__device__ __half g_proj[(size_t)6*NB*NC*NPIX];
__device__ __half g_win_l[(size_t)NB*NL*64*64];   // [b][l][n][c]
__device__ __half g_win_h[(size_t)NB*NL*64*64];
__device__ float g_mean[NB*NC];
__device__ float g_sgate[NB*NC];

// ---------------- packed f32x2 helpers ----------------
__device__ __forceinline__ u64 pk2(float lo, float hi) {
    u64 r;
    asm("mov.b64 %0,{%1,%2};" : "=l"(r) : "f"(lo), "f"(hi));
    return r;
}
__device__ __forceinline__ void upk2(float& lo, float& hi, u64 v) {
    asm("mov.b64 {%0,%1},%2;" : "=f"(lo), "=f"(hi) : "l"(v));
}
__device__ __forceinline__ u64 fma2(u64 a, u64 b, u64 c) {
    u64 d;
    asm("fma.rn.f32x2 %0,%1,%2,%3;" : "=l"(d) : "l"(a), "l"(b), "l"(c));
    return d;
}
__device__ __forceinline__ uint32_t f2h2(float a, float b) {
    __half2 h = __floats2half2_rn(a, b);
    return *(uint32_t*)&h;
}

// ---------------- tf32 mma helpers ----------------
__device__ __forceinline__ uint32_t tf32r(float f) {
    uint32_t r;
    asm("cvt.rna.tf32.f32 %0,%1;" : "=r"(r) : "f"(f));
    return r;
}
__device__ __forceinline__ float ex2(float x) {
    float r;
    asm("ex2.approx.f32 %0,%1;" : "=f"(r) : "f"(x));
    return r;
}
__device__ __forceinline__ void mma8(float* d, const uint32_t* a, uint32_t b0, uint32_t b1) {
    asm volatile(
        "mma.sync.aligned.m16n8k8.row.col.f32.tf32.tf32.f32 "
        "{%0,%1,%2,%3},{%4,%5,%6,%7},{%8,%9},{%0,%1,%2,%3};"
        : "+f"(d[0]), "+f"(d[1]), "+f"(d[2]), "+f"(d[3])
        : "r"(a[0]), "r"(a[1]), "r"(a[2]), "r"(a[3]), "r"(b0), "r"(b1));
}

// ---------------- SE: per-channel global mean ----------------
__global__ void mean_kernel(const float* __restrict__ high) {
    int bc = blockIdx.x;
    const float* p = high + (size_t)bc * NPIX;
    float s = 0.f;
    for (int i = threadIdx.x; i < NPIX; i += 256) s += p[i];
    __shared__ float red[256];
    red[threadIdx.x] = s; __syncthreads();
    for (int k = 128; k > 0; k >>= 1) {
        if (threadIdx.x < k) red[threadIdx.x] += red[threadIdx.x + k];
        __syncthreads();
    }
    if (threadIdx.x == 0) g_mean[bc] = red[0] * (1.f/NPIX);
}

// ---------------- SE: gate per (b,c) ----------------
__global__ void se_kernel(const float* __restrict__ w10, const float* __restrict__ w20,
                          const float* __restrict__ w11, const float* __restrict__ w21,
                          const float* __restrict__ w12, const float* __restrict__ w22) {
    int t = threadIdx.x;
    int b = t >> 6, c = t & 63;
    int g  = (c < 22) ? 0 : ((c < 43) ? 1 : 2);
    int of = (g == 0) ? 0 : ((g == 1) ? 22 : 43);
    int gc = (g == 0) ? 22 : 21;
    const float* w1 = (g==0) ? w10 : ((g==1) ? w11 : w12);
    const float* w2 = (g==0) ? w20 : ((g==1) ? w21 : w22);
    float h = 0.f;
    for (int j = 0; j < gc; j++) h += g_mean[b*64 + of + j] * w1[j];
    h = fmaxf(h, 0.f);
    float v = h * w2[c - of];
    g_sgate[t] = 1.f / (1.f + __expf(-v));
}

// ---------------- projections: 3 stages of 2 weights; fp16 outputs ----------------
#define WTS 68
#define QS 0.36067376022224085f
__global__ void __launch_bounds__(256,3) proj_kernel(
    const float* __restrict__ low, const float* __restrict__ high,
    const float* __restrict__ w_ql, const float* __restrict__ w_kh,
    const float* __restrict__ w_vh, const float* __restrict__ w_qh,
    const float* __restrict__ w_kl, const float* __restrict__ w_vl)
{
    extern __shared__ float sm[];
    float* xl = sm;            // 4096
    float* xh = sm + 4096;     // 4096
    float* wb = sm + 8192;     // 2 * 64*68 = 8704

    int t = threadIdx.x;
    int pix0 = blockIdx.x * 64;
    int b = blockIdx.y;

    for (int i4 = t; i4 < 1024; i4 += 256) {
        int c = i4 >> 4, pp = (i4 & 15) * 4;
        size_t gi = (size_t)(b*NC + c)*NPIX + pix0 + pp;
        float4 vl = *(const float4*)(low + gi);
        float4 vh = *(const float4*)(high + gi);
        float gt = g_sgate[b*64 + c];
        vh.x *= gt; vh.y *= gt; vh.z *= gt; vh.w *= gt;
        *(float4*)(xl + c*64 + pp) = vl;
        *(float4*)(xh + c*64 + pp) = vh;
    }

    int ot = (t >> 4) << 2;
    int nb = (t & 15) << 2;

    // s0: (0=ql[xl,QS], 4=kl[xl])   s1: (1=kh[xh], 2=vh[xh])   s2: (5=vl[xl], 3=qh[xh,QS])
    const float* WA[3]; const float* WB[3];
    WA[0] = w_ql; WB[0] = w_kl;
    WA[1] = w_kh; WB[1] = w_vh;
    WA[2] = w_vl; WB[2] = w_qh;
    const int slotA[3] = {0, 1, 5};
    const int slotB[3] = {4, 2, 3};

    for (int s = 0; s < 3; s++) {
        __syncthreads();
        bool scaleA = (s == 0), scaleB = (s == 2);
        for (int i = t; i < 8192; i += 256) {
            int p = i >> 12, j = i & 4095;
            int o = j >> 6, c = j & 63;
            float wv = (p == 0) ? WA[s][j] : WB[s][j];
            if ((p == 0 && scaleA) || (p == 1 && scaleB)) wv *= QS;
            wb[p*4352 + c*WTS + o] = wv;
        }
        __syncthreads();

        const float* XA = (s == 2) ? xl : ((s == 0) ? xl : xh);
        const float* XB = (s == 2) ? xh : ((s == 0) ? xl : xh);
        bool sameX = (s != 2);

        u64 acc2[2][4][2];
        #pragma unroll
        for (int p = 0; p < 2; p++)
            #pragma unroll
            for (int n = 0; n < 4; n++) { acc2[p][n][0] = 0ULL; acc2[p][n][1] = 0ULL; }

        if (sameX) {
            #pragma unroll 4
            for (int c = 0; c < 64; c++) {
                float4 x4 = *(const float4*)(XA + c*64 + nb);
                u64 xd0 = pk2(x4.x, x4.x);
                u64 xd1 = pk2(x4.y, x4.y);
                u64 xd2 = pk2(x4.z, x4.z);
                u64 xd3 = pk2(x4.w, x4.w);
                #pragma unroll
                for (int p = 0; p < 2; p++) {
                    ulonglong2 w2v = *(const ulonglong2*)(wb + p*4352 + c*WTS + ot);
                    acc2[p][0][0] = fma2(xd0, w2v.x, acc2[p][0][0]);
                    acc2[p][0][1] = fma2(xd0, w2v.y, acc2[p][0][1]);
                    acc2[p][1][0] = fma2(xd1, w2v.x, acc2[p][1][0]);
                    acc2[p][1][1] = fma2(xd1, w2v.y, acc2[p][1][1]);
                    acc2[p][2][0] = fma2(xd2, w2v.x, acc2[p][2][0]);
                    acc2[p][2][1] = fma2(xd2, w2v.y, acc2[p][2][1]);
                    acc2[p][3][0] = fma2(xd3, w2v.x, acc2[p][3][0]);
                    acc2[p][3][1] = fma2(xd3, w2v.y, acc2[p][3][1]);
                }
            }
        } else {
            #pragma unroll 4
            for (int c = 0; c < 64; c++) {
                float4 xa4 = *(const float4*)(XA + c*64 + nb);
                float4 xb4 = *(const float4*)(XB + c*64 + nb);
                u64 xa0 = pk2(xa4.x, xa4.x), xa1 = pk2(xa4.y, xa4.y);
                u64 xa2 = pk2(xa4.z, xa4.z), xa3 = pk2(xa4.w, xa4.w);
                u64 xb0 = pk2(xb4.x, xb4.x), xb1 = pk2(xb4.y, xb4.y);
                u64 xb2 = pk2(xb4.z, xb4.z), xb3 = pk2(xb4.w, xb4.w);
                ulonglong2 wa = *(const ulonglong2*)(wb + c*WTS + ot);
                ulonglong2 wv = *(const ulonglong2*)(wb + 4352 + c*WTS + ot);
                acc2[0][0][0] = fma2(xa0, wa.x, acc2[0][0][0]);
                acc2[0][0][1] = fma2(xa0, wa.y, acc2[0][0][1]);
                acc2[0][1][0] = fma2(xa1, wa.x, acc2[0][1][0]);
                acc2[0][1][1] = fma2(xa1, wa.y, acc2[0][1][1]);
                acc2[0][2][0] = fma2(xa2, wa.x, acc2[0][2][0]);
                acc2[0][2][1] = fma2(xa2, wa.y, acc2[0][2][1]);
                acc2[0][3][0] = fma2(xa3, wa.x, acc2[0][3][0]);
                acc2[0][3][1] = fma2(xa3, wa.y, acc2[0][3][1]);
                acc2[1][0][0] = fma2(xb0, wv.x, acc2[1][0][0]);
                acc2[1][0][1] = fma2(xb0, wv.y, acc2[1][0][1]);
                acc2[1][1][0] = fma2(xb1, wv.x, acc2[1][1][0]);
                acc2[1][1][1] = fma2(xb1, wv.y, acc2[1][1][1]);
                acc2[1][2][0] = fma2(xb2, wv.x, acc2[1][2][0]);
                acc2[1][2][1] = fma2(xb2, wv.y, acc2[1][2][1]);
                acc2[1][3][0] = fma2(xb3, wv.x, acc2[1][3][0]);
                acc2[1][3][1] = fma2(xb3, wv.y, acc2[1][3][1]);
            }
        }

        int sl[2]; sl[0] = slotA[s]; sl[1] = slotB[s];
        #pragma unroll
        for (int p = 0; p < 2; p++) {
            float lo0[4], hi0[4], lo1[4], hi1[4];
            #pragma unroll
            for (int n = 0; n < 4; n++) {
                upk2(lo0[n], hi0[n], acc2[p][n][0]);
                upk2(lo1[n], hi1[n], acc2[p][n][1]);
            }
            size_t base = (size_t)sl[p]*NB*NC*NPIX + (size_t)(b*NC)*NPIX + pix0 + nb;
            uint2 s0, s1, s2, s3;
            s0.x = f2h2(lo0[0], lo0[1]); s0.y = f2h2(lo0[2], lo0[3]);
            s1.x = f2h2(hi0[0], hi0[1]); s1.y = f2h2(hi0[2], hi0[3]);
            s2.x = f2h2(lo1[0], lo1[1]); s2.y = f2h2(lo1[2], lo1[3]);
            s3.x = f2h2(hi1[0], hi1[1]); s3.y = f2h2(hi1[2], hi1[3]);
            *(uint2*)(g_proj + base + (size_t)(ot+0)*NPIX) = s0;
            *(uint2*)(g_proj + base + (size_t)(ot+1)*NPIX) = s1;
            *(uint2*)(g_proj + base + (size_t)(ot+2)*NPIX) = s2;
            *(uint2*)(g_proj + base + (size_t)(ot+3)*NPIX) = s3;
        }
    }
}

// ---------------- attention: tf32 MMA v4, fp16-staged inputs/outputs ----------------
#define KSTR 72
#define VSTR 68
#define KHSZ (16*KSTR)
#define VHSZ (16*VSTR)
#define SMEM_ATTN_WORDS (4*KHSZ + 4*VHSZ + 256)

__global__ void __launch_bounds__(128, 5) attn_kernel()
{
    extern __shared__ uint32_t smu[];
    uint32_t* kbuf = smu;                      // 4*KHSZ
    uint32_t* vbuf = smu + 4*KHSZ;             // 4*VHSZ
    float*    sinv = (float*)(smu + 4*KHSZ + 4*VHSZ);   // 256

    int t = threadIdx.x;
    int l = blockIdx.x, dir = blockIdx.y, b = blockIdx.z;
    int y0 = (l / NWIN) * 4, x0 = (l % NWIN) * 4;

    // stage + convert K and V (fp16 -> tf32)
    for (int i4 = t; i4 < 2048; i4 += 128) {
        int p = i4 >> 10, rem = i4 & 1023;       // p: 0=k 1=v
        int slot = dir*3 + 1 + p;
        int c = rem >> 4, q4 = rem & 15;
        int r = q4 >> 1, cc = (q4 & 1) * 4;
        int n = r*8 + cc;
        int h = c >> 4, d = c & 15;
        size_t gi = ((size_t)slot*NB*NC + (size_t)(b*NC + c))*NPIX + (size_t)(y0 + r)*NW + x0 + cc;
        uint2 raw = *(const uint2*)(g_proj + gi);
        float2 f0 = __half22float2(*(__half2*)&raw.x);
        float2 f1 = __half22float2(*(__half2*)&raw.y);
        uint4 e;
        e.x = tf32r(f0.x); e.y = tf32r(f0.y); e.z = tf32r(f1.x); e.w = tf32r(f1.y);
        uint32_t* dst = (p ? (vbuf + h*VHSZ + d*VSTR) : (kbuf + h*KHSZ + d*KSTR)) + n;
        *(uint4*)dst = e;
    }
    __syncthreads();

    int h = t >> 5, lane = t & 31;
    int gid = lane >> 2, tig = lane & 3;
    int sig = (gid & 1) ? ((gid >> 1) + 4) : (gid >> 1);   // sigma(gid)

    const uint32_t* kf = kbuf + h*KHSZ;
    const uint32_t* vf = vbuf + h*VHSZ;
    const __half* Qg = g_proj + ((size_t)(dir ? 3 : 0)*NB*NC + (size_t)(b*NC + h*16))*NPIX;
    __half* wdst = (dir ? g_win_h : g_win_l) + (size_t)(b*NL + l)*4096;  // [n][c]

    #pragma unroll
    for (int nt = 0; nt < 4; nt++) {
        int nbase = nt*16;
        size_t pA = (size_t)(y0 + 2*nt)*NW + x0 + gid;   // pixel for n = nbase+gid
        size_t pB = pA + NW;                              // pixel for n = nbase+gid+8

        // ---- Q A-fragments (fp16 -> tf32) from gmem, 2 d-chunks ----
        uint32_t qh[2][4];
        #pragma unroll
        for (int kq = 0; kq < 2; kq++) {
            int d0 = kq*8 + tig;
            qh[kq][0] = tf32r(__half2float(Qg[(size_t)d0*NPIX     + pA]));
            qh[kq][1] = tf32r(__half2float(Qg[(size_t)d0*NPIX     + pB]));
            qh[kq][2] = tf32r(__half2float(Qg[(size_t)(d0+4)*NPIX + pA]));
            qh[kq][3] = tf32r(__half2float(Qg[(size_t)(d0+4)*NPIX + pB]));
        }

        float o0[4] = {0.f,0.f,0.f,0.f};   // O tile, n = nbase + 0..7
        float o1[4] = {0.f,0.f,0.f,0.f};   // O tile, n = nbase + 8..15
        float rs0 = 0.f, rs1 = 0.f;

        #pragma unroll
        for (int m8 = 0; m8 < 64; m8 += 8) {
            // ---- S tile [n16 x m8]: 2 MMA ----
            float c[4] = {0.f,0.f,0.f,0.f};
            #pragma unroll
            for (int kq = 0; kq < 2; kq++) {
                uint32_t kk0 = kf[(kq*8+tig)*KSTR   + m8 + sig];
                uint32_t kk1 = kf[(kq*8+tig+4)*KSTR + m8 + sig];
                mma8(c, qh[kq], kk0, kk1);
            }
            // ---- exp, rowsum, P 1-term ----
            float e0 = ex2(c[0]), e1 = ex2(c[1]), e2 = ex2(c[2]), e3 = ex2(c[3]);
            rs0 += e0 + e1;
            rs1 += e2 + e3;
            uint32_t p0 = tf32r(e0), p1 = tf32r(e1), p2 = tf32r(e2), p3 = tf32r(e3);
            // ---- V A-fragments (pre-converted) ----
            uint32_t va[4];
            va[0] = vf[gid*VSTR     + m8 + tig    ];
            va[1] = vf[(gid+8)*VSTR + m8 + tig    ];
            va[2] = vf[gid*VSTR     + m8 + tig + 4];
            va[3] = vf[(gid+8)*VSTR + m8 + tig + 4];
            // ---- AV: 2 MMA ----
            mma8(o0, va, p0, p1);
            mma8(o1, va, p2, p3);
        }
        // ---- softmax denominators: reduce across the 4 tig lanes ----
        rs0 += __shfl_xor_sync(0xffffffffu, rs0, 1);
        rs0 += __shfl_xor_sync(0xffffffffu, rs0, 2);
        rs1 += __shfl_xor_sync(0xffffffffu, rs1, 1);
        rs1 += __shfl_xor_sync(0xffffffffu, rs1, 2);
        if (tig == 0) {
            sinv[h*64 + nbase + gid]     = 1.f / rs0;
            sinv[h*64 + nbase + gid + 8] = 1.f / rs1;
        }
        __syncwarp();
        // ---- normalize + per-window store (fp16) ----
        #pragma unroll
        for (int jt = 0; jt < 2; jt++) {
            const float* ot = jt ? o1 : o0;
            int n0 = nbase + jt*8 + 2*tig;
            float inv0 = sinv[h*64 + n0];
            float inv1 = sinv[h*64 + n0 + 1];
            __half* w0 = wdst + (size_t)n0*64 + h*16;
            w0[gid]          = __float2half_rn(ot[0]*inv0);
            w0[64 + gid]     = __float2half_rn(ot[1]*inv1);
            w0[gid + 8]      = __float2half_rn(ot[2]*inv0);
            w0[64 + gid + 8] = __float2half_rn(ot[3]*inv1);
        }
    }
}

// ---------------- epilogue: vectorized fp16 gather, 1x1 proj + residual ----------------
__global__ void __launch_bounds__(256) epi_kernel(
    const float* __restrict__ low, const float* __restrict__ high,
    const float* __restrict__ wpl, const float* __restrict__ wph,
    float* __restrict__ out)
{
    extern __shared__ float sm[];
    float* tl = sm;                  // 64*65 = 4160
    float* th = sm + 4160;           // 4160
    float* wl = sm + 8320;           // 64*68 = 4352
    float* wh = sm + 8320 + 4352;    // 4352 (total 17024 floats)

    int t = threadIdx.x;
    int chunk = blockIdx.x;          // 1024 chunks: 256 per batch, 64 px each
    int b = chunk >> 8;
    int pix0 = (chunk & 255) * 64;

    for (int i = t; i < 4096; i += 256) {
        int o = i >> 6, c = i & 63;
        wl[c*WTS + o] = wpl[i];
        wh[c*WTS + o] = wph[i];
    }

    // gather: 16 threads per pixel, 4 channels per thread (8B fp16 loads)
    int cg = (t & 15) * 4;           // channel group base
    int pxg = t >> 4;                // 0..15
    for (int it = 0; it < 4; it++) {
        int px = it*16 + pxg;
        int pix = pix0 + px;
        int y = pix >> 7, x = pix & 127;
        int iyl = (y >= 8) ? ((y - 4) >> 2) : 0;
        int iyh = y >> 2; if (iyh > 30) iyh = 30;
        int ixl = (x >= 8) ? ((x - 4) >> 2) : 0;
        int ixh = x >> 2; if (ixh > 30) ixh = 30;
        float4 sl = make_float4(0.f,0.f,0.f,0.f);
        float4 sh = make_float4(0.f,0.f,0.f,0.f);
        for (int iy = iyl; iy <= iyh; iy++) {
            for (int ix = ixl; ix <= ixh; ix++) {
                int ll = iy*NWIN + ix;
                int n = (y - 4*iy)*8 + (x - 4*ix);
                size_t base = ((size_t)(b*NL + ll)*64 + n)*64 + cg;
                uint2 ra = *(const uint2*)(g_win_l + base);
                uint2 rb = *(const uint2*)(g_win_h + base);
                float2 a0 = __half22float2(*(__half2*)&ra.x);
                float2 a1 = __half22float2(*(__half2*)&ra.y);
                float2 b0 = __half22float2(*(__half2*)&rb.x);
                float2 b1 = __half22float2(*(__half2*)&rb.y);
                sl.x += a0.x; sl.y += a0.y; sl.z += a1.x; sl.w += a1.y;
                sh.x += b0.x; sh.y += b0.y; sh.z += b1.x; sh.w += b1.y;
            }
        }
        float ic = 1.f / (float)((iyh - iyl + 1) * (ixh - ixl + 1));
        tl[(cg+0)*65 + px] = sl.x * ic;
        tl[(cg+1)*65 + px] = sl.y * ic;
        tl[(cg+2)*65 + px] = sl.z * ic;
        tl[(cg+3)*65 + px] = sl.w * ic;
        th[(cg+0)*65 + px] = sh.x * ic;
        th[(cg+1)*65 + px] = sh.y * ic;
        th[(cg+2)*65 + px] = sh.z * ic;
        th[(cg+3)*65 + px] = sh.w * ic;
    }
    __syncthreads();

    int px = t & 63, og = (t >> 6) * 16;
    u64 rl2[8], rh2[8];
    #pragma unroll
    for (int j = 0; j < 8; j++) { rl2[j] = 0ULL; rh2[j] = 0ULL; }

    #pragma unroll 4
    for (int c = 0; c < 64; c++) {
        float tv = tl[c*65 + px];
        float hv = th[c*65 + px];
        u64 tv2 = pk2(tv, tv);
        u64 hv2 = pk2(hv, hv);
        const ulonglong2* wlr = (const ulonglong2*)(wl + c*WTS + og);
        const ulonglong2* whr = (const ulonglong2*)(wh + c*WTS + og);
        #pragma unroll
        for (int o4 = 0; o4 < 4; o4++) {
            ulonglong2 a2 = wlr[o4];
            ulonglong2 b2 = whr[o4];
            rl2[o4*2]   = fma2(tv2, a2.x, rl2[o4*2]);
            rl2[o4*2+1] = fma2(tv2, a2.y, rl2[o4*2+1]);
            rh2[o4*2]   = fma2(hv2, b2.x, rh2[o4*2]);
            rh2[o4*2+1] = fma2(hv2, b2.y, rh2[o4*2+1]);
        }
    }
    size_t half = (size_t)NB*NC*NPIX;
    int pix = pix0 + px;
    #pragma unroll
    for (int j = 0; j < 8; j++) {
        float a, bb; upk2(a, bb, rl2[j]);
        float c2, d2; upk2(c2, d2, rh2[j]);
        int o0 = og + j*2;
        size_t gi0 = (size_t)(b*NC + o0)*NPIX + pix;
        size_t gi1 = (size_t)(b*NC + o0 + 1)*NPIX + pix;
        out[gi0]        = low[gi0]  + a;
        out[gi1]        = low[gi1]  + bb;
        out[half + gi0] = high[gi0] + c2;
        out[half + gi1] = high[gi1] + d2;
    }
}

extern "C" void kernel_launch(void* const* d_in, const int* in_sizes, int n_in,
                              void* d_out, int out_size)
{
    (void)in_sizes; (void)n_in; (void)out_size;
    const float* low  = (const float*)d_in[0];
    const float* high = (const float*)d_in[1];
    const float* w_ql = (const float*)d_in[2];
    const float* w_kh = (const float*)d_in[3];
    const float* w_vh = (const float*)d_in[4];
    const float* w_qh = (const float*)d_in[5];
    const float* w_kl = (const float*)d_in[6];
    const float* w_vl = (const float*)d_in[7];
    const float* wpl  = (const float*)d_in[8];
    const float* wph  = (const float*)d_in[9];

    int proj_smem = (8192 + 8704) * 4;        // 67.6 KB
    int attn_smem = SMEM_ATTN_WORDS * 4;      // ~36.9 KB
    int epi_smem  = 17024 * 4;                // 66.5 KB

    cudaFuncSetAttribute(proj_kernel, cudaFuncAttributeMaxDynamicSharedMemorySize, proj_smem);
    cudaFuncSetAttribute(attn_kernel, cudaFuncAttributeMaxDynamicSharedMemorySize, attn_smem);
    cudaFuncSetAttribute(epi_kernel,  cudaFuncAttributeMaxDynamicSharedMemorySize, epi_smem);

    mean_kernel<<<NB*NC, 256>>>(high);
    se_kernel<<<1, 256>>>((const float*)d_in[10], (const float*)d_in[11],
                          (const float*)d_in[12], (const float*)d_in[13],
                          (const float*)d_in[14], (const float*)d_in[15]);
    proj_kernel<<<dim3(NPIX/64, NB), 256, proj_smem>>>(low, high, w_ql, w_kh, w_vh, w_qh, w_kl, w_vl);
    attn_kernel<<<dim3(NL, 2, NB), 128, attn_smem>>>();
    epi_kernel<<<1024, 256, epi_smem>>>(low, high, wpl, wph, (float*)d_out);
}

// round 17
// speedup vs baseline: 1.4139x; 1.0719x over previous
#include <cuda_runtime.h>
#include <cuda_fp16.h>
#include <cstdint>

#define NB 4
#define NC 64
#define NH 128
#define NW 128
#define NPIX (NH*NW)
#define NWIN 31
#define NL (NWIN*NWIN)

typedef unsigned long long u64;

// proj slot order: 0=ql 1=kh 2=vh 3=qh 4=kl 5=vl  (dir0 uses 0,1,2; dir1 uses 3,4,5)
__device__ __half g_proj[(size_t)6*NB*NC*NPIX];
__device__ __half g_win_l[(size_t)NB*NL*64*64];   // [b][l][n][c]
__device__ __half g_win_h[(size_t)NB*NL*64*64];
__device__ float g_mean[NB*NC];
__device__ float g_sgate[NB*NC];

// ---------------- packed f32x2 helpers ----------------
__device__ __forceinline__ u64 pk2(float lo, float hi) {
    u64 r;
    asm("mov.b64 %0,{%1,%2};" : "=l"(r) : "f"(lo), "f"(hi));
    return r;
}
__device__ __forceinline__ void upk2(float& lo, float& hi, u64 v) {
    asm("mov.b64 {%0,%1},%2;" : "=f"(lo), "=f"(hi) : "l"(v));
}
__device__ __forceinline__ u64 fma2(u64 a, u64 b, u64 c) {
    u64 d;
    asm("fma.rn.f32x2 %0,%1,%2,%3;" : "=l"(d) : "l"(a), "l"(b), "l"(c));
    return d;
}
__device__ __forceinline__ uint32_t f2h2(float a, float b) {
    __half2 h = __floats2half2_rn(a, b);
    return *(uint32_t*)&h;
}

// ---------------- fp16 mma helpers ----------------
__device__ __forceinline__ float ex2(float x) {
    float r;
    asm("ex2.approx.f32 %0,%1;" : "=f"(r) : "f"(x));
    return r;
}
// pack two f32 -> f16x2 (lo -> low half, hi -> high half)
__device__ __forceinline__ uint32_t fpk(float lo, float hi) {
    uint32_t r;
    asm("cvt.rn.f16x2.f32 %0,%1,%2;" : "=r"(r) : "f"(hi), "f"(lo));
    return r;
}
// pack two halves (lo -> low)
__device__ __forceinline__ uint32_t hpk(__half lo, __half hi) {
    __half2 h = __halves2half2(lo, hi);
    return *(uint32_t*)&h;
}
__device__ __forceinline__ void mma16(float* d, const uint32_t* a, uint32_t b0, uint32_t b1) {
    asm volatile(
        "mma.sync.aligned.m16n8k16.row.col.f32.f16.f16.f32 "
        "{%0,%1,%2,%3},{%4,%5,%6,%7},{%8,%9},{%0,%1,%2,%3};"
        : "+f"(d[0]), "+f"(d[1]), "+f"(d[2]), "+f"(d[3])
        : "r"(a[0]), "r"(a[1]), "r"(a[2]), "r"(a[3]), "r"(b0), "r"(b1));
}

// ---------------- SE: per-channel global mean ----------------
__global__ void mean_kernel(const float* __restrict__ high) {
    int bc = blockIdx.x;
    const float* p = high + (size_t)bc * NPIX;
    float s = 0.f;
    for (int i = threadIdx.x; i < NPIX; i += 256) s += p[i];
    __shared__ float red[256];
    red[threadIdx.x] = s; __syncthreads();
    for (int k = 128; k > 0; k >>= 1) {
        if (threadIdx.x < k) red[threadIdx.x] += red[threadIdx.x + k];
        __syncthreads();
    }
    if (threadIdx.x == 0) g_mean[bc] = red[0] * (1.f/NPIX);
}

// ---------------- SE: gate per (b,c) ----------------
__global__ void se_kernel(const float* __restrict__ w10, const float* __restrict__ w20,
                          const float* __restrict__ w11, const float* __restrict__ w21,
                          const float* __restrict__ w12, const float* __restrict__ w22) {
    int t = threadIdx.x;
    int b = t >> 6, c = t & 63;
    int g  = (c < 22) ? 0 : ((c < 43) ? 1 : 2);
    int of = (g == 0) ? 0 : ((g == 1) ? 22 : 43);
    int gc = (g == 0) ? 22 : 21;
    const float* w1 = (g==0) ? w10 : ((g==1) ? w11 : w12);
    const float* w2 = (g==0) ? w20 : ((g==1) ? w21 : w22);
    float h = 0.f;
    for (int j = 0; j < gc; j++) h += g_mean[b*64 + of + j] * w1[j];
    h = fmaxf(h, 0.f);
    float v = h * w2[c - of];
    g_sgate[t] = 1.f / (1.f + __expf(-v));
}

// ---------------- projections: 3 stages of 2 weights; fp16 outputs ----------------
#define WTS 68
#define QS 0.36067376022224085f
__global__ void __launch_bounds__(256,3) proj_kernel(
    const float* __restrict__ low, const float* __restrict__ high,
    const float* __restrict__ w_ql, const float* __restrict__ w_kh,
    const float* __restrict__ w_vh, const float* __restrict__ w_qh,
    const float* __restrict__ w_kl, const float* __restrict__ w_vl)
{
    extern __shared__ float sm[];
    float* xl = sm;            // 4096
    float* xh = sm + 4096;     // 4096
    float* wb = sm + 8192;     // 2 * 64*68 = 8704

    int t = threadIdx.x;
    int pix0 = blockIdx.x * 64;
    int b = blockIdx.y;

    for (int i4 = t; i4 < 1024; i4 += 256) {
        int c = i4 >> 4, pp = (i4 & 15) * 4;
        size_t gi = (size_t)(b*NC + c)*NPIX + pix0 + pp;
        float4 vl = *(const float4*)(low + gi);
        float4 vh = *(const float4*)(high + gi);
        float gt = g_sgate[b*64 + c];
        vh.x *= gt; vh.y *= gt; vh.z *= gt; vh.w *= gt;
        *(float4*)(xl + c*64 + pp) = vl;
        *(float4*)(xh + c*64 + pp) = vh;
    }

    int ot = (t >> 4) << 2;
    int nb = (t & 15) << 2;

    // s0: (0=ql[xl,QS], 4=kl[xl])   s1: (1=kh[xh], 2=vh[xh])   s2: (5=vl[xl], 3=qh[xh,QS])
    const float* WA[3]; const float* WB[3];
    WA[0] = w_ql; WB[0] = w_kl;
    WA[1] = w_kh; WB[1] = w_vh;
    WA[2] = w_vl; WB[2] = w_qh;
    const int slotA[3] = {0, 1, 5};
    const int slotB[3] = {4, 2, 3};

    for (int s = 0; s < 3; s++) {
        __syncthreads();
        bool scaleA = (s == 0), scaleB = (s == 2);
        for (int i = t; i < 8192; i += 256) {
            int p = i >> 12, j = i & 4095;
            int o = j >> 6, c = j & 63;
            float wv = (p == 0) ? WA[s][j] : WB[s][j];
            if ((p == 0 && scaleA) || (p == 1 && scaleB)) wv *= QS;
            wb[p*4352 + c*WTS + o] = wv;
        }
        __syncthreads();

        const float* XA = (s == 2) ? xl : ((s == 0) ? xl : xh);
        const float* XB = (s == 2) ? xh : ((s == 0) ? xl : xh);
        bool sameX = (s != 2);

        u64 acc2[2][4][2];
        #pragma unroll
        for (int p = 0; p < 2; p++)
            #pragma unroll
            for (int n = 0; n < 4; n++) { acc2[p][n][0] = 0ULL; acc2[p][n][1] = 0ULL; }

        if (sameX) {
            #pragma unroll 4
            for (int c = 0; c < 64; c++) {
                float4 x4 = *(const float4*)(XA + c*64 + nb);
                u64 xd0 = pk2(x4.x, x4.x);
                u64 xd1 = pk2(x4.y, x4.y);
                u64 xd2 = pk2(x4.z, x4.z);
                u64 xd3 = pk2(x4.w, x4.w);
                #pragma unroll
                for (int p = 0; p < 2; p++) {
                    ulonglong2 w2v = *(const ulonglong2*)(wb + p*4352 + c*WTS + ot);
                    acc2[p][0][0] = fma2(xd0, w2v.x, acc2[p][0][0]);
                    acc2[p][0][1] = fma2(xd0, w2v.y, acc2[p][0][1]);
                    acc2[p][1][0] = fma2(xd1, w2v.x, acc2[p][1][0]);
                    acc2[p][1][1] = fma2(xd1, w2v.y, acc2[p][1][1]);
                    acc2[p][2][0] = fma2(xd2, w2v.x, acc2[p][2][0]);
                    acc2[p][2][1] = fma2(xd2, w2v.y, acc2[p][2][1]);
                    acc2[p][3][0] = fma2(xd3, w2v.x, acc2[p][3][0]);
                    acc2[p][3][1] = fma2(xd3, w2v.y, acc2[p][3][1]);
                }
            }
        } else {
            #pragma unroll 4
            for (int c = 0; c < 64; c++) {
                float4 xa4 = *(const float4*)(XA + c*64 + nb);
                float4 xb4 = *(const float4*)(XB + c*64 + nb);
                u64 xa0 = pk2(xa4.x, xa4.x), xa1 = pk2(xa4.y, xa4.y);
                u64 xa2 = pk2(xa4.z, xa4.z), xa3 = pk2(xa4.w, xa4.w);
                u64 xb0 = pk2(xb4.x, xb4.x), xb1 = pk2(xb4.y, xb4.y);
                u64 xb2 = pk2(xb4.z, xb4.z), xb3 = pk2(xb4.w, xb4.w);
                ulonglong2 wa = *(const ulonglong2*)(wb + c*WTS + ot);
                ulonglong2 wv = *(const ulonglong2*)(wb + 4352 + c*WTS + ot);
                acc2[0][0][0] = fma2(xa0, wa.x, acc2[0][0][0]);
                acc2[0][0][1] = fma2(xa0, wa.y, acc2[0][0][1]);
                acc2[0][1][0] = fma2(xa1, wa.x, acc2[0][1][0]);
                acc2[0][1][1] = fma2(xa1, wa.y, acc2[0][1][1]);
                acc2[0][2][0] = fma2(xa2, wa.x, acc2[0][2][0]);
                acc2[0][2][1] = fma2(xa2, wa.y, acc2[0][2][1]);
                acc2[0][3][0] = fma2(xa3, wa.x, acc2[0][3][0]);
                acc2[0][3][1] = fma2(xa3, wa.y, acc2[0][3][1]);
                acc2[1][0][0] = fma2(xb0, wv.x, acc2[1][0][0]);
                acc2[1][0][1] = fma2(xb0, wv.y, acc2[1][0][1]);
                acc2[1][1][0] = fma2(xb1, wv.x, acc2[1][1][0]);
                acc2[1][1][1] = fma2(xb1, wv.y, acc2[1][1][1]);
                acc2[1][2][0] = fma2(xb2, wv.x, acc2[1][2][0]);
                acc2[1][2][1] = fma2(xb2, wv.y, acc2[1][2][1]);
                acc2[1][3][0] = fma2(xb3, wv.x, acc2[1][3][0]);
                acc2[1][3][1] = fma2(xb3, wv.y, acc2[1][3][1]);
            }
        }

        int sl[2]; sl[0] = slotA[s]; sl[1] = slotB[s];
        #pragma unroll
        for (int p = 0; p < 2; p++) {
            float lo0[4], hi0[4], lo1[4], hi1[4];
            #pragma unroll
            for (int n = 0; n < 4; n++) {
                upk2(lo0[n], hi0[n], acc2[p][n][0]);
                upk2(lo1[n], hi1[n], acc2[p][n][1]);
            }
            size_t base = (size_t)sl[p]*NB*NC*NPIX + (size_t)(b*NC)*NPIX + pix0 + nb;
            uint2 s0, s1, s2, s3;
            s0.x = f2h2(lo0[0], lo0[1]); s0.y = f2h2(lo0[2], lo0[3]);
            s1.x = f2h2(hi0[0], hi0[1]); s1.y = f2h2(hi0[2], hi0[3]);
            s2.x = f2h2(lo1[0], lo1[1]); s2.y = f2h2(lo1[2], lo1[3]);
            s3.x = f2h2(hi1[0], hi1[1]); s3.y = f2h2(hi1[2], hi1[3]);
            *(uint2*)(g_proj + base + (size_t)(ot+0)*NPIX) = s0;
            *(uint2*)(g_proj + base + (size_t)(ot+1)*NPIX) = s1;
            *(uint2*)(g_proj + base + (size_t)(ot+2)*NPIX) = s2;
            *(uint2*)(g_proj + base + (size_t)(ot+3)*NPIX) = s3;
        }
    }
}

// ---------------- attention: fp16 MMA m16n8k16 (identity fragment chaining) ----------------
#define KTS 24   // halves per kT row (16 data + 8 pad); 12 words -> conflict-free
#define VTS 72   // halves per V row  (64 data + 8 pad); 36 words -> conflict-free
#define KHH (64*KTS)   // halves per head, K^T [m][d]
#define VHH (16*VTS)   // halves per head, V  [d][m]
#define SMEM_ATTN_BYTES (4*(KHH + VHH)*2 + 256*4)

__global__ void __launch_bounds__(128, 8) attn_kernel()
{
    extern __shared__ __half smh[];
    __half* kbuf = smh;                       // 4*KHH
    __half* vbuf = smh + 4*KHH;               // 4*VHH
    float*  sinv = (float*)(smh + 4*(KHH + VHH));   // 256 floats

    int t = threadIdx.x;
    int l = blockIdx.x, dir = blockIdx.y, b = blockIdx.z;
    int y0 = (l / NWIN) * 4, x0 = (l % NWIN) * 4;

    // stage K (transposed to [m][d]) and V ([d][m]) — raw fp16 copies
    for (int i4 = t; i4 < 2048; i4 += 128) {
        int p = i4 >> 10, rem = i4 & 1023;       // p: 0=k 1=v
        int slot = dir*3 + 1 + p;
        int c = rem >> 4, q4 = rem & 15;
        int r = q4 >> 1, cc = (q4 & 1) * 4;
        int n = r*8 + cc;
        int h = c >> 4, d = c & 15;
        size_t gi = ((size_t)slot*NB*NC + (size_t)(b*NC + c))*NPIX + (size_t)(y0 + r)*NW + x0 + cc;
        uint2 raw = *(const uint2*)(g_proj + gi);
        if (p == 0) {
            __half2 h0 = *(__half2*)&raw.x;
            __half2 h1 = *(__half2*)&raw.y;
            __half* kd = kbuf + h*KHH + n*KTS + d;
            kd[0*KTS] = __low2half(h0);
            kd[1*KTS] = __high2half(h0);
            kd[2*KTS] = __low2half(h1);
            kd[3*KTS] = __high2half(h1);
        } else {
            *(uint2*)(vbuf + h*VHH + d*VTS + n) = raw;
        }
    }
    __syncthreads();

    int h = t >> 5, lane = t & 31;
    int gid = lane >> 2, tig = lane & 3;

    const __half* kf = kbuf + h*KHH;
    const __half* vf = vbuf + h*VHH;
    const __half* Qg = g_proj + ((size_t)(dir ? 3 : 0)*NB*NC + (size_t)(b*NC + h*16))*NPIX;
    __half* wdst = (dir ? g_win_h : g_win_l) + (size_t)(b*NL + l)*4096;  // [n][c]

    #pragma unroll
    for (int nt = 0; nt < 4; nt++) {
        int nbase = nt*16;
        size_t pA = (size_t)(y0 + 2*nt)*NW + x0 + gid;   // pixel for n = nbase+gid
        size_t pB = pA + NW;                              // pixel for n = nbase+gid+8

        // ---- Q A-fragments: rows n = gid/gid+8, cols d = 2tig..2tig+1, 2tig+8..+9 ----
        uint32_t qa[4];
        qa[0] = hpk(Qg[(size_t)(2*tig)*NPIX   + pA], Qg[(size_t)(2*tig+1)*NPIX + pA]);
        qa[1] = hpk(Qg[(size_t)(2*tig)*NPIX   + pB], Qg[(size_t)(2*tig+1)*NPIX + pB]);
        qa[2] = hpk(Qg[(size_t)(2*tig+8)*NPIX + pA], Qg[(size_t)(2*tig+9)*NPIX + pA]);
        qa[3] = hpk(Qg[(size_t)(2*tig+8)*NPIX + pB], Qg[(size_t)(2*tig+9)*NPIX + pB]);

        float o0[4] = {0.f,0.f,0.f,0.f};   // O tile, n = nbase + 0..7
        float o1[4] = {0.f,0.f,0.f,0.f};   // O tile, n = nbase + 8..15
        float rs0 = 0.f, rs1 = 0.f;

        #pragma unroll
        for (int m16 = 0; m16 < 64; m16 += 16) {
            // ---- two S tiles [n16 x m8]: A=Q (k=d=16), B=K^T half2 loads ----
            float ca[4] = {0.f,0.f,0.f,0.f};
            float cb[4] = {0.f,0.f,0.f,0.f};
            uint32_t kb0a = *(const uint32_t*)(kf + (m16+gid)*KTS   + 2*tig);
            uint32_t kb1a = *(const uint32_t*)(kf + (m16+gid)*KTS   + 2*tig + 8);
            uint32_t kb0b = *(const uint32_t*)(kf + (m16+8+gid)*KTS + 2*tig);
            uint32_t kb1b = *(const uint32_t*)(kf + (m16+8+gid)*KTS + 2*tig + 8);
            mma16(ca, qa, kb0a, kb1a);
            mma16(cb, qa, kb0b, kb1b);
            // ---- exp, rowsum ----
            float ea0 = ex2(ca[0]), ea1 = ex2(ca[1]), ea2 = ex2(ca[2]), ea3 = ex2(ca[3]);
            float eb0 = ex2(cb[0]), eb1 = ex2(cb[1]), eb2 = ex2(cb[2]), eb3 = ex2(cb[3]);
            rs0 += (ea0 + ea1) + (eb0 + eb1);
            rs1 += (ea2 + ea3) + (eb2 + eb3);
            // ---- P fp16 B-fragments (identity chaining: C cols pair = B k pair) ----
            uint32_t p00 = fpk(ea0, ea1);   // n-half0 (rows gid),   k = m16+2tig..+1
            uint32_t p01 = fpk(eb0, eb1);   // n-half0,              k = m16+8+2tig..+1
            uint32_t p10 = fpk(ea2, ea3);   // n-half1 (rows gid+8)
            uint32_t p11 = fpk(eb2, eb3);
            // ---- V A-fragments: rows d = gid/gid+8, cols m = m16+2tig pairs ----
            uint32_t va[4];
            va[0] = *(const uint32_t*)(vf + gid*VTS     + m16 + 2*tig);
            va[1] = *(const uint32_t*)(vf + (gid+8)*VTS + m16 + 2*tig);
            va[2] = *(const uint32_t*)(vf + gid*VTS     + m16 + 8 + 2*tig);
            va[3] = *(const uint32_t*)(vf + (gid+8)*VTS + m16 + 8 + 2*tig);
            // ---- AV: O[d16 x n8] += V * P (k = m16 chunk) ----
            mma16(o0, va, p00, p01);
            mma16(o1, va, p10, p11);
        }
        // ---- softmax denominators: reduce across the 4 tig lanes ----
        rs0 += __shfl_xor_sync(0xffffffffu, rs0, 1);
        rs0 += __shfl_xor_sync(0xffffffffu, rs0, 2);
        rs1 += __shfl_xor_sync(0xffffffffu, rs1, 1);
        rs1 += __shfl_xor_sync(0xffffffffu, rs1, 2);
        if (tig == 0) {
            sinv[h*64 + nbase + gid]     = 1.f / rs0;
            sinv[h*64 + nbase + gid + 8] = 1.f / rs1;
        }
        __syncwarp();
        // ---- normalize + per-window store (fp16) ----
        #pragma unroll
        for (int jt = 0; jt < 2; jt++) {
            const float* ot = jt ? o1 : o0;
            int n0 = nbase + jt*8 + 2*tig;
            float inv0 = sinv[h*64 + n0];
            float inv1 = sinv[h*64 + n0 + 1];
            __half* w0 = wdst + (size_t)n0*64 + h*16;
            w0[gid]          = __float2half_rn(ot[0]*inv0);
            w0[64 + gid]     = __float2half_rn(ot[1]*inv1);
            w0[gid + 8]      = __float2half_rn(ot[2]*inv0);
            w0[64 + gid + 8] = __float2half_rn(ot[3]*inv1);
        }
    }
}

// ---------------- epilogue: vectorized fp16 gather, 1x1 proj + residual ----------------
__global__ void __launch_bounds__(256) epi_kernel(
    const float* __restrict__ low, const float* __restrict__ high,
    const float* __restrict__ wpl, const float* __restrict__ wph,
    float* __restrict__ out)
{
    extern __shared__ float sm[];
    float* tl = sm;                  // 64*65 = 4160
    float* th = sm + 4160;           // 4160
    float* wl = sm + 8320;           // 64*68 = 4352
    float* wh = sm + 8320 + 4352;    // 4352 (total 17024 floats)

    int t = threadIdx.x;
    int chunk = blockIdx.x;          // 1024 chunks: 256 per batch, 64 px each
    int b = chunk >> 8;
    int pix0 = (chunk & 255) * 64;

    for (int i = t; i < 4096; i += 256) {
        int o = i >> 6, c = i & 63;
        wl[c*WTS + o] = wpl[i];
        wh[c*WTS + o] = wph[i];
    }

    // gather: 16 threads per pixel, 4 channels per thread (8B fp16 loads)
    int cg = (t & 15) * 4;
    int pxg = t >> 4;
    for (int it = 0; it < 4; it++) {
        int px = it*16 + pxg;
        int pix = pix0 + px;
        int y = pix >> 7, x = pix & 127;
        int iyl = (y >= 8) ? ((y - 4) >> 2) : 0;
        int iyh = y >> 2; if (iyh > 30) iyh = 30;
        int ixl = (x >= 8) ? ((x - 4) >> 2) : 0;
        int ixh = x >> 2; if (ixh > 30) ixh = 30;
        float4 sl = make_float4(0.f,0.f,0.f,0.f);
        float4 sh = make_float4(0.f,0.f,0.f,0.f);
        for (int iy = iyl; iy <= iyh; iy++) {
            for (int ix = ixl; ix <= ixh; ix++) {
                int ll = iy*NWIN + ix;
                int n = (y - 4*iy)*8 + (x - 4*ix);
                size_t base = ((size_t)(b*NL + ll)*64 + n)*64 + cg;
                uint2 ra = *(const uint2*)(g_win_l + base);
                uint2 rb = *(const uint2*)(g_win_h + base);
                float2 a0 = __half22float2(*(__half2*)&ra.x);
                float2 a1 = __half22float2(*(__half2*)&ra.y);
                float2 b0 = __half22float2(*(__half2*)&rb.x);
                float2 b1 = __half22float2(*(__half2*)&rb.y);
                sl.x += a0.x; sl.y += a0.y; sl.z += a1.x; sl.w += a1.y;
                sh.x += b0.x; sh.y += b0.y; sh.z += b1.x; sh.w += b1.y;
            }
        }
        float ic = 1.f / (float)((iyh - iyl + 1) * (ixh - ixl + 1));
        tl[(cg+0)*65 + px] = sl.x * ic;
        tl[(cg+1)*65 + px] = sl.y * ic;
        tl[(cg+2)*65 + px] = sl.z * ic;
        tl[(cg+3)*65 + px] = sl.w * ic;
        th[(cg+0)*65 + px] = sh.x * ic;
        th[(cg+1)*65 + px] = sh.y * ic;
        th[(cg+2)*65 + px] = sh.z * ic;
        th[(cg+3)*65 + px] = sh.w * ic;
    }
    __syncthreads();

    int px = t & 63, og = (t >> 6) * 16;
    u64 rl2[8], rh2[8];
    #pragma unroll
    for (int j = 0; j < 8; j++) { rl2[j] = 0ULL; rh2[j] = 0ULL; }

    #pragma unroll 4
    for (int c = 0; c < 64; c++) {
        float tv = tl[c*65 + px];
        float hv = th[c*65 + px];
        u64 tv2 = pk2(tv, tv);
        u64 hv2 = pk2(hv, hv);
        const ulonglong2* wlr = (const ulonglong2*)(wl + c*WTS + og);
        const ulonglong2* whr = (const ulonglong2*)(wh + c*WTS + og);
        #pragma unroll
        for (int o4 = 0; o4 < 4; o4++) {
            ulonglong2 a2 = wlr[o4];
            ulonglong2 b2 = whr[o4];
            rl2[o4*2]   = fma2(tv2, a2.x, rl2[o4*2]);
            rl2[o4*2+1] = fma2(tv2, a2.y, rl2[o4*2+1]);
            rh2[o4*2]   = fma2(hv2, b2.x, rh2[o4*2]);
            rh2[o4*2+1] = fma2(hv2, b2.y, rh2[o4*2+1]);
        }
    }
    size_t half = (size_t)NB*NC*NPIX;
    int pix = pix0 + px;
    #pragma unroll
    for (int j = 0; j < 8; j++) {
        float a, bb; upk2(a, bb, rl2[j]);
        float c2, d2; upk2(c2, d2, rh2[j]);
        int o0 = og + j*2;
        size_t gi0 = (size_t)(b*NC + o0)*NPIX + pix;
        size_t gi1 = (size_t)(b*NC + o0 + 1)*NPIX + pix;
        out[gi0]        = low[gi0]  + a;
        out[gi1]        = low[gi1]  + bb;
        out[half + gi0] = high[gi0] + c2;
        out[half + gi1] = high[gi1] + d2;
    }
}

extern "C" void kernel_launch(void* const* d_in, const int* in_sizes, int n_in,
                              void* d_out, int out_size)
{
    (void)in_sizes; (void)n_in; (void)out_size;
    const float* low  = (const float*)d_in[0];
    const float* high = (const float*)d_in[1];
    const float* w_ql = (const float*)d_in[2];
    const float* w_kh = (const float*)d_in[3];
    const float* w_vh = (const float*)d_in[4];
    const float* w_qh = (const float*)d_in[5];
    const float* w_kl = (const float*)d_in[6];
    const float* w_vl = (const float*)d_in[7];
    const float* wpl  = (const float*)d_in[8];
    const float* wph  = (const float*)d_in[9];

    int proj_smem = (8192 + 8704) * 4;        // 67.6 KB
    int attn_smem = SMEM_ATTN_BYTES;          // ~22.5 KB
    int epi_smem  = 17024 * 4;                // 66.5 KB

    cudaFuncSetAttribute(proj_kernel, cudaFuncAttributeMaxDynamicSharedMemorySize, proj_smem);
    cudaFuncSetAttribute(attn_kernel, cudaFuncAttributeMaxDynamicSharedMemorySize, attn_smem);
    cudaFuncSetAttribute(epi_kernel,  cudaFuncAttributeMaxDynamicSharedMemorySize, epi_smem);

    mean_kernel<<<NB*NC, 256>>>(high);
    se_kernel<<<1, 256>>>((const float*)d_in[10], (const float*)d_in[11],
                          (const float*)d_in[12], (const float*)d_in[13],
                          (const float*)d_in[14], (const float*)d_in[15]);
    proj_kernel<<<dim3(NPIX/64, NB), 256, proj_smem>>>(low, high, w_ql, w_kh, w_vh, w_qh, w_kl, w_vl);
    attn_kernel<<<dim3(NL, 2, NB), 128, attn_smem>>>();
    epi_kernel<<<1024, 256, epi_smem>>>(low, high, wpl, wph, (float*)d_out);
}